// round 8
// baseline (speedup 1.0000x reference)
#include <cuda_runtime.h>
#include <cuda_bf16.h>
#include <mma.h>
#include <cstdint>

using namespace nvcuda;

#define B_  512
#define T_  512
#define I_  128
#define H_  512
#define C_  128
#define OT_ 128

// persistent kernel tiling: grid 8x16 = 128 CTAs, CTA tile 64x32, 8 warps (4x2), K-chunk 64
#define GX   8
#define GY   16
#define NCTA 128
#define NT   256
#define BM   64
#define BN   32
#define KC   64
#define LD   72
#define LDC  36

// ---------------- device globals (allocation-free scratch) ----------------
__device__ __nv_bfloat16 g_xh[(size_t)B_ * T_ * I_];
__device__ __nv_bfloat16 g_xl[(size_t)B_ * T_ * I_];
__device__ __nv_bfloat16 g_Whh_h[H_ * H_], g_Whh_l[H_ * H_];
__device__ __nv_bfloat16 g_Wih_h[H_ * I_], g_Wih_l[H_ * I_];
__device__ __nv_bfloat16 g_f1_h[H_ * H_],  g_f1_l[H_ * H_];
__device__ __nv_bfloat16 g_f2_h[C_ * H_],  g_f2_l[C_ * H_];
__device__ __nv_bfloat16 g_h0h[B_ * H_], g_h0l[B_ * H_];
__device__ __nv_bfloat16 g_h1h[B_ * H_], g_h1l[B_ * H_];
__device__ __nv_bfloat16 g_nhh[(size_t)OT_ * B_ * H_];     // decoder nh slab [s][b][h]
__device__ __nv_bfloat16 g_nhl[(size_t)OT_ * B_ * H_];
__device__ __nv_bfloat16 g_mh[(size_t)OT_ * B_ * H_];      // fc1 out slab
__device__ __nv_bfloat16 g_ml[(size_t)OT_ * B_ * H_];
__device__ float         g_bias2[H_];                      // b_ih + b_hh
__device__ int           g_len64;
__device__ unsigned      g_bar_arrive, g_bar_gen;

// ---------------- prologue kernels ----------------
__global__ void split_kernel(const float* __restrict__ s, __nv_bfloat16* __restrict__ hi,
                             __nv_bfloat16* __restrict__ lo, long n4) {
    long i = (long)blockIdx.x * blockDim.x + threadIdx.x;
    if (i >= n4) return;
    float4 v = reinterpret_cast<const float4*>(s)[i];
    union { __nv_bfloat16 b[4]; uint2 u; } h, l;
    float a[4] = { v.x, v.y, v.z, v.w };
#pragma unroll
    for (int j = 0; j < 4; j++) {
        h.b[j] = __float2bfloat16(a[j]);
        l.b[j] = __float2bfloat16(a[j] - __bfloat162float(h.b[j]));
    }
    reinterpret_cast<uint2*>(hi)[i] = h.u;
    reinterpret_cast<uint2*>(lo)[i] = l.u;
}

__global__ void init_kernel(const float* __restrict__ b_ih, const float* __restrict__ b_hh) {
    int i = blockIdx.x * blockDim.x + threadIdx.x;
    if (i < H_) g_bias2[i] = b_ih[i] + b_hh[i];
    if (i < B_ * H_) { g_h0h[i] = __float2bfloat16(0.f); g_h0l[i] = __float2bfloat16(0.f); }
    if (i == 0) { g_bar_arrive = 0u; g_bar_gen = 0u; }
}

// lengths dtype sniff: int64 buffers have all odd int32 words == 0 (values < 512)
__global__ void detect_len_kernel(const int* p) {
    int is64 = 1;
    for (int i = 0; i < 32; i++)
        if (p[2 * i + 1] != 0) is64 = 0;
    g_len64 = is64;
}

// ---------------- grid-wide barrier (all 128 CTAs resident) ----------------
__device__ __forceinline__ void grid_sync(unsigned& gen) {
    __syncthreads();
    if (threadIdx.x == 0) {
        __threadfence();
        if (atomicAdd(&g_bar_arrive, 1u) == NCTA - 1) {
            atomicExch(&g_bar_arrive, 0u);
            __threadfence();
            atomicAdd(&g_bar_gen, 1u);
        } else {
            while (atomicAdd(&g_bar_gen, 0u) <= gen) __nanosleep(64);
            __threadfence();
        }
    }
    gen++;
    __syncthreads();
}

// ---------------- persistent serial-chain kernel ----------------
// SMEM layout (bytes):
//   sW : [2 plane][10 chunk][32][72] bf16   = 92160   (chunks 0-7: Whh, 8-9: Wih)
//   sA : [2 buf][2 plane][64][72]   bf16    = 36864
//   sC : [64][36] f32                       =  9216
#define SMEM_PERS 138240

__global__ void __launch_bounds__(NT) rnn_persistent(
    const __nv_bfloat16* __restrict__ xh, const __nv_bfloat16* __restrict__ xl,
    const void* __restrict__ lengths)
{
    extern __shared__ __align__(16) char smem[];
    __nv_bfloat16* sW = reinterpret_cast<__nv_bfloat16*>(smem);
    __nv_bfloat16* sA = reinterpret_cast<__nv_bfloat16*>(smem + 92160);
    float*         sC = reinterpret_cast<float*>(smem + 129024);

    const int tid = threadIdx.x;
    const int wid = tid >> 5;
    const int wy  = wid >> 1;       // 0..3 -> m offset 16*wy
    const int wx  = wid & 1;        // 0..1 -> n offset 16*wx
    const int m0  = blockIdx.x * BM;
    const int n0  = blockIdx.y * BN;

    // ---- load resident weight tiles (once) ----
    {
        const int r = tid >> 3, cc = tid & 7;          // 32 rows x 8 uint4
        for (int pl = 0; pl < 2; pl++) {
            const __nv_bfloat16* wh = pl ? g_Whh_l : g_Whh_h;
            for (int c = 0; c < 8; c++)
                *reinterpret_cast<uint4*>(sW + (pl * 10 + c) * 2304 + r * LD + cc * 8) =
                    *reinterpret_cast<const uint4*>(wh + (size_t)(n0 + r) * H_ + c * KC + cc * 8);
            const __nv_bfloat16* wi = pl ? g_Wih_l : g_Wih_h;
            for (int c = 0; c < 2; c++)
                *reinterpret_cast<uint4*>(sW + (pl * 10 + 8 + c) * 2304 + r * LD + cc * 8) =
                    *reinterpret_cast<const uint4*>(wi + (size_t)(n0 + r) * I_ + c * KC + cc * 8);
        }
    }

    // epilogue constants: thread -> (row er, 8-col group)
    const int er  = tid >> 2;
    const int ec0 = (tid & 3) * 8;
    const int em  = m0 + er;
    const int enb = n0 + ec0;
    float biasr[8];
#pragma unroll
    for (int j = 0; j < 8; j++) biasr[j] = g_bias2[enb + j];
    const long long mylen = g_len64 ? ((const long long*)lengths)[em]
                                    : (long long)((const int*)lengths)[em];
    __syncthreads();

    unsigned gen = 0;
    uint4 ra[2], rl[2];

    auto prefetch_h = [&](const __nv_bfloat16* Ah, const __nv_bfloat16* Al, int c) {
#pragma unroll
        for (int i = 0; i < 2; i++) {
            int id = tid + i * NT; int r = id >> 3, cc = id & 7;
            size_t g = (size_t)(m0 + r) * H_ + c * KC + cc * 8;
            ra[i] = __ldcg(reinterpret_cast<const uint4*>(Ah + g));
            rl[i] = __ldcg(reinterpret_cast<const uint4*>(Al + g));
        }
    };
    auto prefetch_x = [&](int t, int cx) {
#pragma unroll
        for (int i = 0; i < 2; i++) {
            int id = tid + i * NT; int r = id >> 3, cc = id & 7;
            size_t g = (size_t)(m0 + r) * (T_ * I_) + (size_t)t * I_ + cx * KC + cc * 8;
            ra[i] = __ldcg(reinterpret_cast<const uint4*>(xh + g));
            rl[i] = __ldcg(reinterpret_cast<const uint4*>(xl + g));
        }
    };
    auto stores = [&](int buf) {
#pragma unroll
        for (int i = 0; i < 2; i++) {
            int id = tid + i * NT; int r = id >> 3, cc = id & 7;
            *reinterpret_cast<uint4*>(sA + buf * 9216 +        r * LD + cc * 8) = ra[i];
            *reinterpret_cast<uint4*>(sA + buf * 9216 + 4608 + r * LD + cc * 8) = rl[i];
        }
    };

    // GEMM over nch K-chunks (chunks >= 8 read from x at step t); result -> sC
    auto run_gemm = [&](const __nv_bfloat16* Ah, const __nv_bfloat16* Al, int nch, int t) {
        wmma::fragment<wmma::accumulator, 16, 16, 16, float> acc;
        wmma::fill_fragment(acc, 0.f);
        prefetch_h(Ah, Al, 0);
        for (int c = 0; c < nch; c++) {
            const int buf = c & 1;
            stores(buf);
            __syncthreads();
            if (c + 1 < nch) {
                if (c + 1 < 8) prefetch_h(Ah, Al, c + 1);
                else           prefetch_x(t, c + 1 - 8);
            }
#pragma unroll
            for (int ks = 0; ks < 4; ks++) {
                wmma::fragment<wmma::matrix_a, 16, 16, 16, __nv_bfloat16, wmma::row_major> aH, aL;
                wmma::fragment<wmma::matrix_b, 16, 16, 16, __nv_bfloat16, wmma::col_major> bH, bL;
                wmma::load_matrix_sync(aH, sA + buf * 9216 +        (wy * 16) * LD + ks * 16, LD);
                wmma::load_matrix_sync(aL, sA + buf * 9216 + 4608 + (wy * 16) * LD + ks * 16, LD);
                wmma::load_matrix_sync(bH, sW + (0 * 10 + c) * 2304 + (wx * 16) * LD + ks * 16, LD);
                wmma::load_matrix_sync(bL, sW + (1 * 10 + c) * 2304 + (wx * 16) * LD + ks * 16, LD);
                wmma::mma_sync(acc, aH, bH, acc);
                wmma::mma_sync(acc, aH, bL, acc);
                wmma::mma_sync(acc, aL, bH, acc);
            }
        }
        wmma::store_matrix_sync(sC + (wy * 16) * LDC + wx * 16, acc, LDC, wmma::mem_row_major);
        __syncthreads();
    };

    union P { __nv_bfloat16 b[8]; uint4 u; };

    // ---- encoder: 512 serial steps, x@Wih fused via resident chunks 8-9 ----
    for (int t = 0; t < T_; t++) {
        const __nv_bfloat16* Ah = (t & 1) ? g_h1h : g_h0h;
        const __nv_bfloat16* Al = (t & 1) ? g_h1l : g_h0l;
        __nv_bfloat16* Oh = (t & 1) ? g_h0h : g_h1h;
        __nv_bfloat16* Ol = (t & 1) ? g_h0l : g_h1l;
        run_gemm(Ah, Al, 10, t);

        float v[8];
#pragma unroll
        for (int j = 0; j < 2; j++)
            *reinterpret_cast<float4*>(v + j * 4) =
                *reinterpret_cast<const float4*>(sC + er * LDC + ec0 + j * 4);
        P ph, pl;
        if ((long long)t < mylen) {
#pragma unroll
            for (int j = 0; j < 8; j++) {
                float z = tanhf(v[j] + biasr[j]);
                __nv_bfloat16 hb = __float2bfloat16(z);
                ph.b[j] = hb;
                pl.b[j] = __float2bfloat16(z - __bfloat162float(hb));
            }
        } else {   // frozen row: exact bit copy (L2 reads — h addresses recur)
            ph.u = __ldcg(reinterpret_cast<const uint4*>(Ah + (size_t)em * H_ + enb));
            pl.u = __ldcg(reinterpret_cast<const uint4*>(Al + (size_t)em * H_ + enb));
        }
        *reinterpret_cast<uint4*>(Oh + (size_t)em * H_ + enb) = ph.u;
        *reinterpret_cast<uint4*>(Ol + (size_t)em * H_ + enb) = pl.u;
        grid_sync(gen);
    }

    // ---- decoder h-chain: 128 serial steps into nh slab (final h is in h0) ----
    const size_t BH = (size_t)B_ * H_;
    for (int s = 0; s < OT_; s++) {
        const __nv_bfloat16* Ah = (s == 0) ? g_h0h : g_nhh + (size_t)(s - 1) * BH;
        const __nv_bfloat16* Al = (s == 0) ? g_h0l : g_nhl + (size_t)(s - 1) * BH;
        run_gemm(Ah, Al, 8, 0);

        float v[8];
#pragma unroll
        for (int j = 0; j < 2; j++)
            *reinterpret_cast<float4*>(v + j * 4) =
                *reinterpret_cast<const float4*>(sC + er * LDC + ec0 + j * 4);
        P ph, pl;
#pragma unroll
        for (int j = 0; j < 8; j++) {
            float z = tanhf(v[j] + biasr[j]);
            __nv_bfloat16 hb = __float2bfloat16(z);
            ph.b[j] = hb;
            pl.b[j] = __float2bfloat16(z - __bfloat162float(hb));
        }
        *reinterpret_cast<uint4*>(g_nhh + (size_t)s * BH + (size_t)em * H_ + enb) = ph.u;
        *reinterpret_cast<uint4*>(g_nhl + (size_t)s * BH + (size_t)em * H_ + enb) = pl.u;
        grid_sync(gen);
    }
}

// ---------------- batched FC kernels (parallel; validated R6 structure) ----------------
// MODE 0: fc1: out = relu(A@fc1W^T + b) -> bf16 hi/lo slab
// MODE 1: fc2: out[b][s][:] = A@fc2W^T + b -> fp32 strided (slab row m -> s = m>>9, b = m&511)
template <int MODE>
__global__ void __launch_bounds__(128)
fc_kernel(const __nv_bfloat16* __restrict__ Ah, const __nv_bfloat16* __restrict__ Al,
          const __nv_bfloat16* __restrict__ Bh, const __nv_bfloat16* __restrict__ Bl,
          const float* __restrict__ bias,
          __nv_bfloat16* __restrict__ outh, __nv_bfloat16* __restrict__ outl,
          float* __restrict__ outf)
{
    __shared__ __align__(16) char smem[27648];
    __nv_bfloat16* sAh = reinterpret_cast<__nv_bfloat16*>(smem);
    __nv_bfloat16* sAl = reinterpret_cast<__nv_bfloat16*>(smem + 9216);
    __nv_bfloat16* sBh = reinterpret_cast<__nv_bfloat16*>(smem + 18432);
    __nv_bfloat16* sBl = reinterpret_cast<__nv_bfloat16*>(smem + 23040);
    float*         sC  = reinterpret_cast<float*>(smem);

    const int tid = threadIdx.x, wid = tid >> 5;
    const int wy = wid >> 1, wx = wid & 1;
    const int m0 = blockIdx.x * 64;
    const int n0 = blockIdx.y * 32;

    wmma::fragment<wmma::accumulator, 16, 16, 16, float> acc0, acc1;
    wmma::fill_fragment(acc0, 0.f);
    wmma::fill_fragment(acc1, 0.f);

    uint4 raH[4], raL[4], rbH[2], rbL[2];
    auto prefetch = [&](int c) {
        const int k0 = c * KC;
#pragma unroll
        for (int i = 0; i < 4; i++) {
            int id = tid + i * 128; int r = id >> 3, cc = id & 7;
            size_t g = (size_t)(m0 + r) * H_ + k0 + cc * 8;
            raH[i] = *reinterpret_cast<const uint4*>(Ah + g);
            raL[i] = *reinterpret_cast<const uint4*>(Al + g);
        }
#pragma unroll
        for (int i = 0; i < 2; i++) {
            int id = tid + i * 128; int r = id >> 3, cc = id & 7;
            size_t g = (size_t)(n0 + r) * H_ + k0 + cc * 8;
            rbH[i] = *reinterpret_cast<const uint4*>(Bh + g);
            rbL[i] = *reinterpret_cast<const uint4*>(Bl + g);
        }
    };
    auto stores = [&]() {
#pragma unroll
        for (int i = 0; i < 4; i++) {
            int id = tid + i * 128; int r = id >> 3, cc = id & 7;
            *reinterpret_cast<uint4*>(sAh + r * LD + cc * 8) = raH[i];
            *reinterpret_cast<uint4*>(sAl + r * LD + cc * 8) = raL[i];
        }
#pragma unroll
        for (int i = 0; i < 2; i++) {
            int id = tid + i * 128; int r = id >> 3, cc = id & 7;
            *reinterpret_cast<uint4*>(sBh + r * LD + cc * 8) = rbH[i];
            *reinterpret_cast<uint4*>(sBl + r * LD + cc * 8) = rbL[i];
        }
    };

    prefetch(0);
    for (int s = 0; s < H_ / KC; s++) {
        stores();
        __syncthreads();
        if (s + 1 < H_ / KC) prefetch(s + 1);
#pragma unroll
        for (int ks = 0; ks < 4; ks++) {
            const int kk = ks * 16;
            wmma::fragment<wmma::matrix_a, 16, 16, 16, __nv_bfloat16, wmma::row_major> aH0, aH1, aL0, aL1;
            wmma::fragment<wmma::matrix_b, 16, 16, 16, __nv_bfloat16, wmma::col_major> bH, bL;
            wmma::load_matrix_sync(aH0, sAh + (wy * 32)      * LD + kk, LD);
            wmma::load_matrix_sync(aH1, sAh + (wy * 32 + 16) * LD + kk, LD);
            wmma::load_matrix_sync(aL0, sAl + (wy * 32)      * LD + kk, LD);
            wmma::load_matrix_sync(aL1, sAl + (wy * 32 + 16) * LD + kk, LD);
            wmma::load_matrix_sync(bH,  sBh + (wx * 16) * LD + kk, LD);
            wmma::load_matrix_sync(bL,  sBl + (wx * 16) * LD + kk, LD);
            wmma::mma_sync(acc0, aH0, bH, acc0);
            wmma::mma_sync(acc1, aH1, bH, acc1);
            wmma::mma_sync(acc0, aH0, bL, acc0);
            wmma::mma_sync(acc1, aH1, bL, acc1);
            wmma::mma_sync(acc0, aL0, bH, acc0);
            wmma::mma_sync(acc1, aL1, bH, acc1);
        }
        __syncthreads();
    }

    wmma::store_matrix_sync(sC + (wy * 32)      * LDC + wx * 16, acc0, LDC, wmma::mem_row_major);
    wmma::store_matrix_sync(sC + (wy * 32 + 16) * LDC + wx * 16, acc1, LDC, wmma::mem_row_major);
    __syncthreads();

    const int r  = tid >> 1;
    const int c0 = (tid & 1) * 16;
    const int m  = m0 + r;
    const int nb = n0 + c0;

    float v[16];
#pragma unroll
    for (int j = 0; j < 4; j++)
        *reinterpret_cast<float4*>(v + j * 4) =
            *reinterpret_cast<const float4*>(sC + r * LDC + c0 + j * 4);

    if constexpr (MODE == 0) {
        union P8 { __nv_bfloat16 b[8]; uint4 u; } ph[2], pl[2];
#pragma unroll
        for (int j = 0; j < 16; j++) {
            float z = fmaxf(v[j] + bias[nb + j], 0.f);
            __nv_bfloat16 hb = __float2bfloat16(z);
            ph[j >> 3].b[j & 7] = hb;
            pl[j >> 3].b[j & 7] = __float2bfloat16(z - __bfloat162float(hb));
        }
        __nv_bfloat16* oh = outh + (size_t)m * H_ + nb;
        __nv_bfloat16* ol = outl + (size_t)m * H_ + nb;
        reinterpret_cast<uint4*>(oh)[0] = ph[0].u; reinterpret_cast<uint4*>(oh)[1] = ph[1].u;
        reinterpret_cast<uint4*>(ol)[0] = pl[0].u; reinterpret_cast<uint4*>(ol)[1] = pl[1].u;
    } else {
        const int s = m >> 9;
        const int b = m & 511;
        float* op = outf + ((size_t)b * OT_ + s) * C_ + nb;
#pragma unroll
        for (int j = 0; j < 16; j++) v[j] += bias[nb + j];
#pragma unroll
        for (int j = 0; j < 4; j++)
            *reinterpret_cast<float4*>(op + j * 4) = *reinterpret_cast<const float4*>(v + j * 4);
    }
}

// ---------------- host ----------------
extern "C" void kernel_launch(void* const* d_in, const int* in_sizes, int n_in,
                              void* d_out, int out_size) {
    const float* x       = (const float*)d_in[0];
    const void*  lengths = d_in[1];
    const float* W_ih = (const float*)d_in[3];
    const float* W_hh = (const float*)d_in[4];
    const float* b_ih = (const float*)d_in[5];
    const float* b_hh = (const float*)d_in[6];
    const float* fc1W = (const float*)d_in[7];
    const float* fc1b = (const float*)d_in[8];
    const float* fc2W = (const float*)d_in[9];
    const float* fc2b = (const float*)d_in[10];
    float* out = (float*)d_out;

    __nv_bfloat16 *xh, *xl, *WhhH, *WhhL, *WihH, *WihL, *f1H, *f1L, *f2H, *f2L, *nhh, *nhl, *mh, *ml;
    cudaGetSymbolAddress((void**)&xh,   g_xh);    cudaGetSymbolAddress((void**)&xl,   g_xl);
    cudaGetSymbolAddress((void**)&WhhH, g_Whh_h); cudaGetSymbolAddress((void**)&WhhL, g_Whh_l);
    cudaGetSymbolAddress((void**)&WihH, g_Wih_h); cudaGetSymbolAddress((void**)&WihL, g_Wih_l);
    cudaGetSymbolAddress((void**)&f1H,  g_f1_h);  cudaGetSymbolAddress((void**)&f1L,  g_f1_l);
    cudaGetSymbolAddress((void**)&f2H,  g_f2_h);  cudaGetSymbolAddress((void**)&f2L,  g_f2_l);
    cudaGetSymbolAddress((void**)&nhh,  g_nhh);   cudaGetSymbolAddress((void**)&nhl,  g_nhl);
    cudaGetSymbolAddress((void**)&mh,   g_mh);    cudaGetSymbolAddress((void**)&ml,   g_ml);

    auto launch_split = [](const float* s, __nv_bfloat16* h, __nv_bfloat16* l, long n) {
        long n4 = n / 4;
        split_kernel<<<(unsigned)((n4 + 255) / 256), 256>>>(s, h, l, n4);
    };
    launch_split(x,    xh,   xl,   (long)B_ * T_ * I_);
    launch_split(W_hh, WhhH, WhhL, (long)H_ * H_);
    launch_split(W_ih, WihH, WihL, (long)H_ * I_);
    launch_split(fc1W, f1H,  f1L,  (long)H_ * H_);
    launch_split(fc2W, f2H,  f2L,  (long)C_ * H_);
    init_kernel<<<(B_ * H_ + 255) / 256, 256>>>(b_ih, b_hh);
    detect_len_kernel<<<1, 1>>>((const int*)lengths);

    // whole serial chain in ONE persistent kernel
    cudaFuncSetAttribute(rnn_persistent, cudaFuncAttributeMaxDynamicSharedMemorySize, SMEM_PERS);
    rnn_persistent<<<dim3(GX, GY), NT, SMEM_PERS>>>(xh, xl, lengths);

    // batched fc1 / fc2 over all (s, b): M = OT*B = 65536
    fc_kernel<0><<<dim3(OT_ * B_ / 64, H_ / 32), 128>>>(nhh, nhl, f1H, f1L, fc1b, mh, ml, nullptr);
    fc_kernel<1><<<dim3(OT_ * B_ / 64, C_ / 32), 128>>>(mh, ml, f2H, f2L, fc2b, nullptr, nullptr, out);
}

// round 9
// speedup vs baseline: 1.0761x; 1.0761x over previous
#include <cuda_runtime.h>
#include <cuda_bf16.h>
#include <mma.h>
#include <cstdint>

using namespace nvcuda;

#define B_  512
#define T_  512
#define I_  128
#define H_  512
#define C_  128
#define OT_ 128

// persistent kernel: grid 8x16 = 128 CTAs, CTA tile 64x32, 8 warps = 4 m-frags x 2 K-halves
#define GX   8
#define GY   16
#define NCTA 128
#define NT   256
#define KC2  128          // K-chunk for persistent kernel
#define LDK  136          // padded bf16 leading dim (128 + 8)
#define WTILE 4352        // one 32x136 bf16 weight tile, in elements
#define ABUF  17408       // one A buffer (2 planes x 64 x 136), in elements
#define LDC2 36

// fc kernels (parallel, R6-validated): CTA 64x32, 4 warps, KC 64
#define KC   64
#define LD   72
#define LDC  36

// ---------------- device globals (allocation-free scratch) ----------------
__device__ __nv_bfloat16 g_xh[(size_t)B_ * T_ * I_];
__device__ __nv_bfloat16 g_xl[(size_t)B_ * T_ * I_];
__device__ __nv_bfloat16 g_Whh_h[H_ * H_], g_Whh_l[H_ * H_];
__device__ __nv_bfloat16 g_Wih_h[H_ * I_], g_Wih_l[H_ * I_];
__device__ __nv_bfloat16 g_f1_h[H_ * H_],  g_f1_l[H_ * H_];
__device__ __nv_bfloat16 g_f2_h[C_ * H_],  g_f2_l[C_ * H_];
__device__ __nv_bfloat16 g_h0h[B_ * H_], g_h0l[B_ * H_];
__device__ __nv_bfloat16 g_h1h[B_ * H_], g_h1l[B_ * H_];
__device__ __nv_bfloat16 g_nhh[(size_t)OT_ * B_ * H_];     // decoder nh slab [s][b][h]
__device__ __nv_bfloat16 g_nhl[(size_t)OT_ * B_ * H_];
__device__ __nv_bfloat16 g_mh[(size_t)OT_ * B_ * H_];      // fc1 out slab
__device__ __nv_bfloat16 g_ml[(size_t)OT_ * B_ * H_];
__device__ float         g_bias2[H_];                      // b_ih + b_hh
__device__ int           g_len64;
__device__ unsigned      g_bar_arrive, g_bar_gen;

// ---------------- prologue kernels ----------------
__global__ void split_kernel(const float* __restrict__ s, __nv_bfloat16* __restrict__ hi,
                             __nv_bfloat16* __restrict__ lo, long n4) {
    long i = (long)blockIdx.x * blockDim.x + threadIdx.x;
    if (i >= n4) return;
    float4 v = reinterpret_cast<const float4*>(s)[i];
    union { __nv_bfloat16 b[4]; uint2 u; } h, l;
    float a[4] = { v.x, v.y, v.z, v.w };
#pragma unroll
    for (int j = 0; j < 4; j++) {
        h.b[j] = __float2bfloat16(a[j]);
        l.b[j] = __float2bfloat16(a[j] - __bfloat162float(h.b[j]));
    }
    reinterpret_cast<uint2*>(hi)[i] = h.u;
    reinterpret_cast<uint2*>(lo)[i] = l.u;
}

__global__ void init_kernel(const float* __restrict__ b_ih, const float* __restrict__ b_hh) {
    int i = blockIdx.x * blockDim.x + threadIdx.x;
    if (i < H_) g_bias2[i] = b_ih[i] + b_hh[i];
    if (i < B_ * H_) { g_h0h[i] = __float2bfloat16(0.f); g_h0l[i] = __float2bfloat16(0.f); }
    if (i == 0) { g_bar_arrive = 0u; g_bar_gen = 0u; }
}

// lengths dtype sniff: int64 buffers have all odd int32 words == 0 (values < 512)
__global__ void detect_len_kernel(const int* p) {
    int is64 = 1;
    for (int i = 0; i < 32; i++)
        if (p[2 * i + 1] != 0) is64 = 0;
    g_len64 = is64;
}

// ---------------- grid-wide barrier (all 128 CTAs resident) ----------------
__device__ __forceinline__ void grid_sync(unsigned& gen) {
    __syncthreads();
    if (threadIdx.x == 0) {
        __threadfence();
        if (atomicAdd(&g_bar_arrive, 1u) == NCTA - 1) {
            atomicExch(&g_bar_arrive, 0u);
            __threadfence();
            atomicAdd(&g_bar_gen, 1u);
        } else {
            while (atomicAdd(&g_bar_gen, 0u) <= gen) __nanosleep(32);
            __threadfence();
        }
    }
    gen++;
    __syncthreads();
}

// ---------------- persistent serial-chain kernel ----------------
// SMEM (bytes):
//   sW : 10 tiles (2 plane x 5 chunk) x [32][136] bf16 = 87040  (chunks 0-3: Whh, 4: Wih)
//   sA : 2 buf x 2 plane x [64][136] bf16               = 69632
//   sC : 2 K-half slabs x [64][36] f32                  = 18432
#define SMEM_PERS 175104

__global__ void __launch_bounds__(NT, 1) rnn_persistent(
    const __nv_bfloat16* __restrict__ xh, const __nv_bfloat16* __restrict__ xl,
    const void* __restrict__ lengths)
{
    extern __shared__ __align__(16) char smem[];
    __nv_bfloat16* sW = reinterpret_cast<__nv_bfloat16*>(smem);
    __nv_bfloat16* sA = reinterpret_cast<__nv_bfloat16*>(smem + 87040);
    float*         sC = reinterpret_cast<float*>(smem + 156672);

    const int tid = threadIdx.x;
    const int wid = tid >> 5;
    const int wm  = wid & 3;        // m-frag row: 16*wm
    const int wk  = wid >> 2;       // K-half: ks in [wk*4, wk*4+4)
    const int m0  = blockIdx.x * 64;
    const int n0  = blockIdx.y * 32;

    // ---- resident weight tiles (loaded once) ----
    {
        const int r = tid >> 4, cc = tid & 15;     // over 2 iters: 32 rows x 16 uint4
        for (int pl = 0; pl < 2; pl++) {
            const __nv_bfloat16* wh = pl ? g_Whh_l : g_Whh_h;
            for (int c = 0; c < 4; c++)
#pragma unroll
                for (int i = 0; i < 2; i++) {
                    int id = tid + i * NT; int rr = id >> 4, c2 = id & 15;
                    *reinterpret_cast<uint4*>(sW + (pl * 5 + c) * WTILE + rr * LDK + c2 * 8) =
                        *reinterpret_cast<const uint4*>(wh + (size_t)(n0 + rr) * H_ + c * KC2 + c2 * 8);
                }
            const __nv_bfloat16* wi = pl ? g_Wih_l : g_Wih_h;
#pragma unroll
            for (int i = 0; i < 2; i++) {
                int id = tid + i * NT; int rr = id >> 4, c2 = id & 15;
                *reinterpret_cast<uint4*>(sW + (pl * 5 + 4) * WTILE + rr * LDK + c2 * 8) =
                    *reinterpret_cast<const uint4*>(wi + (size_t)(n0 + rr) * I_ + c2 * 8);
            }
        }
        (void)r; (void)cc;
    }

    // epilogue constants: thread -> (row er, 8-col group)
    const int er  = tid >> 2;
    const int ec0 = (tid & 3) * 8;
    const int em  = m0 + er;
    const int enb = n0 + ec0;
    float biasr[8];
#pragma unroll
    for (int j = 0; j < 8; j++) biasr[j] = g_bias2[enb + j];
    const long long mylen = g_len64 ? ((const long long*)lengths)[em]
                                    : (long long)((const int*)lengths)[em];
    __syncthreads();

    unsigned gen = 0;
    uint4 pa[4], pb[4];   // A-chunk prefetch: 4 uint4 per plane per thread

    auto prefetch_h = [&](const __nv_bfloat16* Ah, const __nv_bfloat16* Al, int c) {
#pragma unroll
        for (int i = 0; i < 4; i++) {
            int id = tid + i * NT; int r = id >> 4, cc = id & 15;
            size_t g = (size_t)(m0 + r) * H_ + c * KC2 + cc * 8;
            pa[i] = __ldcg(reinterpret_cast<const uint4*>(Ah + g));
            pb[i] = __ldcg(reinterpret_cast<const uint4*>(Al + g));
        }
    };
    auto prefetch_x = [&](int t) {
#pragma unroll
        for (int i = 0; i < 4; i++) {
            int id = tid + i * NT; int r = id >> 4, cc = id & 15;
            size_t g = (size_t)(m0 + r) * (T_ * I_) + (size_t)t * I_ + cc * 8;
            pa[i] = __ldcg(reinterpret_cast<const uint4*>(xh + g));
            pb[i] = __ldcg(reinterpret_cast<const uint4*>(xl + g));
        }
    };
    auto stores = [&](int buf) {
#pragma unroll
        for (int i = 0; i < 4; i++) {
            int id = tid + i * NT; int r = id >> 4, cc = id & 15;
            *reinterpret_cast<uint4*>(sA + buf * ABUF +        r * LDK + cc * 8) = pa[i];
            *reinterpret_cast<uint4*>(sA + buf * ABUF + 8704 + r * LDK + cc * 8) = pb[i];
        }
    };

    // GEMM over nch chunks of 128 K (chunk 4 = x when nch == 5); result -> sC (2 slabs)
    auto run_gemm = [&](const __nv_bfloat16* Ah, const __nv_bfloat16* Al, int nch, int t) {
        wmma::fragment<wmma::accumulator, 16, 16, 16, float> acc[2][3];
#pragma unroll
        for (int nf = 0; nf < 2; nf++)
#pragma unroll
            for (int p = 0; p < 3; p++) wmma::fill_fragment(acc[nf][p], 0.f);

        prefetch_h(Ah, Al, 0);
        for (int c = 0; c < nch; c++) {
            const int buf = c & 1;
            stores(buf);
            __syncthreads();
            if (c + 1 < nch) {
                if (c + 1 < 4) prefetch_h(Ah, Al, c + 1);
                else           prefetch_x(t);
            }
            const __nv_bfloat16* wH = sW + c * WTILE;
            const __nv_bfloat16* wL = sW + (5 + c) * WTILE;
            const __nv_bfloat16* aBh = sA + buf * ABUF + (wm * 16) * LDK;
            const __nv_bfloat16* aBl = aBh + 8704;
#pragma unroll
            for (int ksl = 0; ksl < 4; ksl++) {
                const int kk = (wk * 4 + ksl) * 16;
                wmma::fragment<wmma::matrix_a, 16, 16, 16, __nv_bfloat16, wmma::row_major> aH, aL;
                wmma::fragment<wmma::matrix_b, 16, 16, 16, __nv_bfloat16, wmma::col_major> bH0, bH1, bL0, bL1;
                wmma::load_matrix_sync(aH,  aBh + kk, LDK);
                wmma::load_matrix_sync(aL,  aBl + kk, LDK);
                wmma::load_matrix_sync(bH0, wH + kk,            LDK);
                wmma::load_matrix_sync(bH1, wH + 16 * LDK + kk, LDK);
                wmma::load_matrix_sync(bL0, wL + kk,            LDK);
                wmma::load_matrix_sync(bL1, wL + 16 * LDK + kk, LDK);
                // 6 independent accumulation chains
                wmma::mma_sync(acc[0][0], aH, bH0, acc[0][0]);
                wmma::mma_sync(acc[1][0], aH, bH1, acc[1][0]);
                wmma::mma_sync(acc[0][1], aH, bL0, acc[0][1]);
                wmma::mma_sync(acc[1][1], aH, bL1, acc[1][1]);
                wmma::mma_sync(acc[0][2], aL, bH0, acc[0][2]);
                wmma::mma_sync(acc[1][2], aL, bH1, acc[1][2]);
            }
        }
        // fold the 3 split-products, park per-K-half partials in sC
#pragma unroll
        for (int nf = 0; nf < 2; nf++) {
#pragma unroll
            for (int e = 0; e < acc[nf][0].num_elements; e++)
                acc[nf][0].x[e] += acc[nf][1].x[e] + acc[nf][2].x[e];
            wmma::store_matrix_sync(sC + wk * 2304 + (wm * 16) * LDC2 + nf * 16,
                                    acc[nf][0], LDC2, wmma::mem_row_major);
        }
        __syncthreads();
    };

    union P { __nv_bfloat16 b[8]; uint4 u; };

    // ---- encoder: 512 serial steps (x @ Wih fused as chunk 4) ----
    for (int t = 0; t < T_; t++) {
        const __nv_bfloat16* Ah = (t & 1) ? g_h1h : g_h0h;
        const __nv_bfloat16* Al = (t & 1) ? g_h1l : g_h0l;
        __nv_bfloat16* Oh = (t & 1) ? g_h0h : g_h1h;
        __nv_bfloat16* Ol = (t & 1) ? g_h0l : g_h1l;
        run_gemm(Ah, Al, 5, t);

        float v[8];
#pragma unroll
        for (int j = 0; j < 8; j++)
            v[j] = sC[er * LDC2 + ec0 + j] + sC[2304 + er * LDC2 + ec0 + j];
        P ph, pl;
        if ((long long)t < mylen) {
#pragma unroll
            for (int j = 0; j < 8; j++) {
                float z = tanhf(v[j] + biasr[j]);
                __nv_bfloat16 hb = __float2bfloat16(z);
                ph.b[j] = hb;
                pl.b[j] = __float2bfloat16(z - __bfloat162float(hb));
            }
        } else {   // frozen row: exact bit copy (L2 reads — addresses recur every 2 steps)
            ph.u = __ldcg(reinterpret_cast<const uint4*>(Ah + (size_t)em * H_ + enb));
            pl.u = __ldcg(reinterpret_cast<const uint4*>(Al + (size_t)em * H_ + enb));
        }
        *reinterpret_cast<uint4*>(Oh + (size_t)em * H_ + enb) = ph.u;
        *reinterpret_cast<uint4*>(Ol + (size_t)em * H_ + enb) = pl.u;
        grid_sync(gen);
    }

    // ---- decoder h-chain: 128 serial steps into nh slab (final h is in h0) ----
    const size_t BH = (size_t)B_ * H_;
    for (int s = 0; s < OT_; s++) {
        const __nv_bfloat16* Ah = (s == 0) ? g_h0h : g_nhh + (size_t)(s - 1) * BH;
        const __nv_bfloat16* Al = (s == 0) ? g_h0l : g_nhl + (size_t)(s - 1) * BH;
        run_gemm(Ah, Al, 4, 0);

        float v[8];
#pragma unroll
        for (int j = 0; j < 8; j++)
            v[j] = sC[er * LDC2 + ec0 + j] + sC[2304 + er * LDC2 + ec0 + j];
        P ph, pl;
#pragma unroll
        for (int j = 0; j < 8; j++) {
            float z = tanhf(v[j] + biasr[j]);
            __nv_bfloat16 hb = __float2bfloat16(z);
            ph.b[j] = hb;
            pl.b[j] = __float2bfloat16(z - __bfloat162float(hb));
        }
        *reinterpret_cast<uint4*>(g_nhh + (size_t)s * BH + (size_t)em * H_ + enb) = ph.u;
        *reinterpret_cast<uint4*>(g_nhl + (size_t)s * BH + (size_t)em * H_ + enb) = pl.u;
        grid_sync(gen);
    }
}

// ---------------- batched FC kernels (parallel; R6-validated) ----------------
// MODE 0: fc1: out = relu(A@fc1W^T + b) -> bf16 hi/lo slab
// MODE 1: fc2: out[b][s][:] = A@fc2W^T + b -> fp32 strided (slab row m -> s = m>>9, b = m&511)
template <int MODE>
__global__ void __launch_bounds__(128)
fc_kernel(const __nv_bfloat16* __restrict__ Ah, const __nv_bfloat16* __restrict__ Al,
          const __nv_bfloat16* __restrict__ Bh, const __nv_bfloat16* __restrict__ Bl,
          const float* __restrict__ bias,
          __nv_bfloat16* __restrict__ outh, __nv_bfloat16* __restrict__ outl,
          float* __restrict__ outf)
{
    __shared__ __align__(16) char smem[27648];
    __nv_bfloat16* sAh = reinterpret_cast<__nv_bfloat16*>(smem);
    __nv_bfloat16* sAl = reinterpret_cast<__nv_bfloat16*>(smem + 9216);
    __nv_bfloat16* sBh = reinterpret_cast<__nv_bfloat16*>(smem + 18432);
    __nv_bfloat16* sBl = reinterpret_cast<__nv_bfloat16*>(smem + 23040);
    float*         sC  = reinterpret_cast<float*>(smem);

    const int tid = threadIdx.x, wid = tid >> 5;
    const int wy = wid >> 1, wx = wid & 1;
    const int m0 = blockIdx.x * 64;
    const int n0 = blockIdx.y * 32;

    wmma::fragment<wmma::accumulator, 16, 16, 16, float> acc0, acc1;
    wmma::fill_fragment(acc0, 0.f);
    wmma::fill_fragment(acc1, 0.f);

    uint4 raH[4], raL[4], rbH[2], rbL[2];
    auto prefetch = [&](int c) {
        const int k0 = c * KC;
#pragma unroll
        for (int i = 0; i < 4; i++) {
            int id = tid + i * 128; int r = id >> 3, cc = id & 7;
            size_t g = (size_t)(m0 + r) * H_ + k0 + cc * 8;
            raH[i] = *reinterpret_cast<const uint4*>(Ah + g);
            raL[i] = *reinterpret_cast<const uint4*>(Al + g);
        }
#pragma unroll
        for (int i = 0; i < 2; i++) {
            int id = tid + i * 128; int r = id >> 3, cc = id & 7;
            size_t g = (size_t)(n0 + r) * H_ + k0 + cc * 8;
            rbH[i] = *reinterpret_cast<const uint4*>(Bh + g);
            rbL[i] = *reinterpret_cast<const uint4*>(Bl + g);
        }
    };
    auto stores = [&]() {
#pragma unroll
        for (int i = 0; i < 4; i++) {
            int id = tid + i * 128; int r = id >> 3, cc = id & 7;
            *reinterpret_cast<uint4*>(sAh + r * LD + cc * 8) = raH[i];
            *reinterpret_cast<uint4*>(sAl + r * LD + cc * 8) = raL[i];
        }
#pragma unroll
        for (int i = 0; i < 2; i++) {
            int id = tid + i * 128; int r = id >> 3, cc = id & 7;
            *reinterpret_cast<uint4*>(sBh + r * LD + cc * 8) = rbH[i];
            *reinterpret_cast<uint4*>(sBl + r * LD + cc * 8) = rbL[i];
        }
    };

    prefetch(0);
    for (int s = 0; s < H_ / KC; s++) {
        stores();
        __syncthreads();
        if (s + 1 < H_ / KC) prefetch(s + 1);
#pragma unroll
        for (int ks = 0; ks < 4; ks++) {
            const int kk = ks * 16;
            wmma::fragment<wmma::matrix_a, 16, 16, 16, __nv_bfloat16, wmma::row_major> aH0, aH1, aL0, aL1;
            wmma::fragment<wmma::matrix_b, 16, 16, 16, __nv_bfloat16, wmma::col_major> bH, bL;
            wmma::load_matrix_sync(aH0, sAh + (wy * 32)      * LD + kk, LD);
            wmma::load_matrix_sync(aH1, sAh + (wy * 32 + 16) * LD + kk, LD);
            wmma::load_matrix_sync(aL0, sAl + (wy * 32)      * LD + kk, LD);
            wmma::load_matrix_sync(aL1, sAl + (wy * 32 + 16) * LD + kk, LD);
            wmma::load_matrix_sync(bH,  sBh + (wx * 16) * LD + kk, LD);
            wmma::load_matrix_sync(bL,  sBl + (wx * 16) * LD + kk, LD);
            wmma::mma_sync(acc0, aH0, bH, acc0);
            wmma::mma_sync(acc1, aH1, bH, acc1);
            wmma::mma_sync(acc0, aH0, bL, acc0);
            wmma::mma_sync(acc1, aH1, bL, acc1);
            wmma::mma_sync(acc0, aL0, bH, acc0);
            wmma::mma_sync(acc1, aL1, bH, acc1);
        }
        __syncthreads();
    }

    wmma::store_matrix_sync(sC + (wy * 32)      * LDC + wx * 16, acc0, LDC, wmma::mem_row_major);
    wmma::store_matrix_sync(sC + (wy * 32 + 16) * LDC + wx * 16, acc1, LDC, wmma::mem_row_major);
    __syncthreads();

    const int r  = tid >> 1;
    const int c0 = (tid & 1) * 16;
    const int m  = m0 + r;
    const int nb = n0 + c0;

    float v[16];
#pragma unroll
    for (int j = 0; j < 4; j++)
        *reinterpret_cast<float4*>(v + j * 4) =
            *reinterpret_cast<const float4*>(sC + r * LDC + c0 + j * 4);

    if constexpr (MODE == 0) {
        union P8 { __nv_bfloat16 b[8]; uint4 u; } ph[2], pl[2];
#pragma unroll
        for (int j = 0; j < 16; j++) {
            float z = fmaxf(v[j] + bias[nb + j], 0.f);
            __nv_bfloat16 hb = __float2bfloat16(z);
            ph[j >> 3].b[j & 7] = hb;
            pl[j >> 3].b[j & 7] = __float2bfloat16(z - __bfloat162float(hb));
        }
        __nv_bfloat16* oh = outh + (size_t)m * H_ + nb;
        __nv_bfloat16* ol = outl + (size_t)m * H_ + nb;
        reinterpret_cast<uint4*>(oh)[0] = ph[0].u; reinterpret_cast<uint4*>(oh)[1] = ph[1].u;
        reinterpret_cast<uint4*>(ol)[0] = pl[0].u; reinterpret_cast<uint4*>(ol)[1] = pl[1].u;
    } else {
        const int s = m >> 9;
        const int b = m & 511;
        float* op = outf + ((size_t)b * OT_ + s) * C_ + nb;
#pragma unroll
        for (int j = 0; j < 16; j++) v[j] += bias[nb + j];
#pragma unroll
        for (int j = 0; j < 4; j++)
            *reinterpret_cast<float4*>(op + j * 4) = *reinterpret_cast<const float4*>(v + j * 4);
    }
}

// ---------------- host ----------------
extern "C" void kernel_launch(void* const* d_in, const int* in_sizes, int n_in,
                              void* d_out, int out_size) {
    const float* x       = (const float*)d_in[0];
    const void*  lengths = d_in[1];
    const float* W_ih = (const float*)d_in[3];
    const float* W_hh = (const float*)d_in[4];
    const float* b_ih = (const float*)d_in[5];
    const float* b_hh = (const float*)d_in[6];
    const float* fc1W = (const float*)d_in[7];
    const float* fc1b = (const float*)d_in[8];
    const float* fc2W = (const float*)d_in[9];
    const float* fc2b = (const float*)d_in[10];
    float* out = (float*)d_out;

    __nv_bfloat16 *xh, *xl, *WhhH, *WhhL, *WihH, *WihL, *f1H, *f1L, *f2H, *f2L, *nhh, *nhl, *mh, *ml;
    cudaGetSymbolAddress((void**)&xh,   g_xh);    cudaGetSymbolAddress((void**)&xl,   g_xl);
    cudaGetSymbolAddress((void**)&WhhH, g_Whh_h); cudaGetSymbolAddress((void**)&WhhL, g_Whh_l);
    cudaGetSymbolAddress((void**)&WihH, g_Wih_h); cudaGetSymbolAddress((void**)&WihL, g_Wih_l);
    cudaGetSymbolAddress((void**)&f1H,  g_f1_h);  cudaGetSymbolAddress((void**)&f1L,  g_f1_l);
    cudaGetSymbolAddress((void**)&f2H,  g_f2_h);  cudaGetSymbolAddress((void**)&f2L,  g_f2_l);
    cudaGetSymbolAddress((void**)&nhh,  g_nhh);   cudaGetSymbolAddress((void**)&nhl,  g_nhl);
    cudaGetSymbolAddress((void**)&mh,   g_mh);    cudaGetSymbolAddress((void**)&ml,   g_ml);

    auto launch_split = [](const float* s, __nv_bfloat16* h, __nv_bfloat16* l, long n) {
        long n4 = n / 4;
        split_kernel<<<(unsigned)((n4 + 255) / 256), 256>>>(s, h, l, n4);
    };
    launch_split(x,    xh,   xl,   (long)B_ * T_ * I_);
    launch_split(W_hh, WhhH, WhhL, (long)H_ * H_);
    launch_split(W_ih, WihH, WihL, (long)H_ * I_);
    launch_split(fc1W, f1H,  f1L,  (long)H_ * H_);
    launch_split(fc2W, f2H,  f2L,  (long)C_ * H_);
    init_kernel<<<(B_ * H_ + 255) / 256, 256>>>(b_ih, b_hh);
    detect_len_kernel<<<1, 1>>>((const int*)lengths);

    // whole serial chain in ONE persistent kernel
    cudaFuncSetAttribute(rnn_persistent, cudaFuncAttributeMaxDynamicSharedMemorySize, SMEM_PERS);
    rnn_persistent<<<dim3(GX, GY), NT, SMEM_PERS>>>(xh, xl, lengths);

    // batched fc1 / fc2 over all (s, b): M = OT*B = 65536
    fc_kernel<0><<<dim3(OT_ * B_ / 64, H_ / 32), 128>>>(nhh, nhl, f1H, f1L, fc1b, mh, ml, nullptr);
    fc_kernel<1><<<dim3(OT_ * B_ / 64, C_ / 32), 128>>>(mh, ml, f2H, f2L, fc2b, nullptr, nullptr, out);
}

// round 10
// speedup vs baseline: 1.0774x; 1.0012x over previous
#include <cuda_runtime.h>
#include <cuda_bf16.h>
#include <mma.h>
#include <cstdint>

using namespace nvcuda;

#define B_  512
#define T_  512
#define I_  128
#define H_  512
#define C_  128
#define OT_ 128

// persistent kernel: grid 8x16 = 128 CTAs, CTA tile 64x32, 8 warps = 4 m-frags x 2 K-halves
#define GX   8
#define GY   16
#define NCTA 128
#define NT   256
#define KC2  128          // K-chunk for persistent kernel
#define LDK  136          // padded bf16 leading dim (128 + 8)
#define WTILE 4352        // one 32x136 bf16 weight tile, in elements
#define ABUF  17408       // one A buffer (2 planes x 64 x 136), in elements
#define LDC2 36

// fc kernels (parallel, R6-validated): CTA 64x32, 4 warps, KC 64
#define KC   64
#define LD   72
#define LDC  36

// ---------------- device globals (allocation-free scratch) ----------------
__device__ __nv_bfloat16 g_xh[(size_t)B_ * T_ * I_];
__device__ __nv_bfloat16 g_xl[(size_t)B_ * T_ * I_];
__device__ __nv_bfloat16 g_Whh_h[H_ * H_], g_Whh_l[H_ * H_];
__device__ __nv_bfloat16 g_Wih_h[H_ * I_], g_Wih_l[H_ * I_];
__device__ __nv_bfloat16 g_f1_h[H_ * H_],  g_f1_l[H_ * H_];
__device__ __nv_bfloat16 g_f2_h[C_ * H_],  g_f2_l[C_ * H_];
__device__ __nv_bfloat16 g_h0h[B_ * H_], g_h0l[B_ * H_];
__device__ __nv_bfloat16 g_h1h[B_ * H_], g_h1l[B_ * H_];
__device__ __nv_bfloat16 g_nhh[(size_t)OT_ * B_ * H_];     // decoder nh slab [s][b][h]
__device__ __nv_bfloat16 g_nhl[(size_t)OT_ * B_ * H_];
__device__ __nv_bfloat16 g_mh[(size_t)OT_ * B_ * H_];      // fc1 out slab
__device__ __nv_bfloat16 g_ml[(size_t)OT_ * B_ * H_];
__device__ float         g_bias2[H_];                      // b_ih + b_hh
__device__ int           g_len64;
__device__ unsigned      g_bar_arrive, g_bar_gen;

// ---------------- prologue kernels ----------------
__global__ void split_kernel(const float* __restrict__ s, __nv_bfloat16* __restrict__ hi,
                             __nv_bfloat16* __restrict__ lo, long n4) {
    long i = (long)blockIdx.x * blockDim.x + threadIdx.x;
    if (i >= n4) return;
    float4 v = reinterpret_cast<const float4*>(s)[i];
    union { __nv_bfloat16 b[4]; uint2 u; } h, l;
    float a[4] = { v.x, v.y, v.z, v.w };
#pragma unroll
    for (int j = 0; j < 4; j++) {
        h.b[j] = __float2bfloat16(a[j]);
        l.b[j] = __float2bfloat16(a[j] - __bfloat162float(h.b[j]));
    }
    reinterpret_cast<uint2*>(hi)[i] = h.u;
    reinterpret_cast<uint2*>(lo)[i] = l.u;
}

__global__ void init_kernel(const float* __restrict__ b_ih, const float* __restrict__ b_hh) {
    int i = blockIdx.x * blockDim.x + threadIdx.x;
    if (i < H_) g_bias2[i] = b_ih[i] + b_hh[i];
    if (i < B_ * H_) { g_h0h[i] = __float2bfloat16(0.f); g_h0l[i] = __float2bfloat16(0.f); }
    if (i == 0) { g_bar_arrive = 0u; g_bar_gen = 0u; }
}

// lengths dtype sniff: int64 buffers have all odd int32 words == 0 (values < 512)
__global__ void detect_len_kernel(const int* p) {
    int is64 = 1;
    for (int i = 0; i < 32; i++)
        if (p[2 * i + 1] != 0) is64 = 0;
    g_len64 = is64;
}

// ---------------- grid-wide barrier (all 128 CTAs resident) ----------------
__device__ __forceinline__ void grid_sync(unsigned& gen) {
    __syncthreads();
    if (threadIdx.x == 0) {
        __threadfence();
        if (atomicAdd(&g_bar_arrive, 1u) == NCTA - 1) {
            atomicExch(&g_bar_arrive, 0u);
            __threadfence();
            atomicAdd(&g_bar_gen, 1u);
        } else {
            while (atomicAdd(&g_bar_gen, 0u) <= gen) __nanosleep(32);
            __threadfence();
        }
    }
    gen++;
    __syncthreads();
}

// ---------------- persistent serial-chain kernel ----------------
// SMEM (bytes):
//   sW : 10 tiles (2 plane x 5 chunk) x [32][136] bf16 = 87040  (chunks 0-3: Whh, 4: Wih)
//   sA : 2 buf x 2 plane x [64][136] bf16               = 69632
//   sC : 2 K-half slabs x [64][36] f32                  = 18432
#define SMEM_PERS 175104

__global__ void __launch_bounds__(NT, 1) rnn_persistent(
    const __nv_bfloat16* __restrict__ xh, const __nv_bfloat16* __restrict__ xl,
    const void* __restrict__ lengths)
{
    extern __shared__ __align__(16) char smem[];
    __nv_bfloat16* sW = reinterpret_cast<__nv_bfloat16*>(smem);
    __nv_bfloat16* sA = reinterpret_cast<__nv_bfloat16*>(smem + 87040);
    float*         sC = reinterpret_cast<float*>(smem + 156672);

    const int tid = threadIdx.x;
    const int wid = tid >> 5;
    const int wm  = wid & 3;        // m-frag row: 16*wm
    const int wk  = wid >> 2;       // K-half: ks in [wk*4, wk*4+4)
    const int m0  = blockIdx.x * 64;
    const int n0  = blockIdx.y * 32;

    // ---- resident weight tiles (loaded once) ----
    {
        const int r = tid >> 4, cc = tid & 15;     // over 2 iters: 32 rows x 16 uint4
        for (int pl = 0; pl < 2; pl++) {
            const __nv_bfloat16* wh = pl ? g_Whh_l : g_Whh_h;
            for (int c = 0; c < 4; c++)
#pragma unroll
                for (int i = 0; i < 2; i++) {
                    int id = tid + i * NT; int rr = id >> 4, c2 = id & 15;
                    *reinterpret_cast<uint4*>(sW + (pl * 5 + c) * WTILE + rr * LDK + c2 * 8) =
                        *reinterpret_cast<const uint4*>(wh + (size_t)(n0 + rr) * H_ + c * KC2 + c2 * 8);
                }
            const __nv_bfloat16* wi = pl ? g_Wih_l : g_Wih_h;
#pragma unroll
            for (int i = 0; i < 2; i++) {
                int id = tid + i * NT; int rr = id >> 4, c2 = id & 15;
                *reinterpret_cast<uint4*>(sW + (pl * 5 + 4) * WTILE + rr * LDK + c2 * 8) =
                    *reinterpret_cast<const uint4*>(wi + (size_t)(n0 + rr) * I_ + c2 * 8);
            }
        }
        (void)r; (void)cc;
    }

    // epilogue constants: thread -> (row er, 8-col group)
    const int er  = tid >> 2;
    const int ec0 = (tid & 3) * 8;
    const int em  = m0 + er;
    const int enb = n0 + ec0;
    float biasr[8];
#pragma unroll
    for (int j = 0; j < 8; j++) biasr[j] = g_bias2[enb + j];
    const long long mylen = g_len64 ? ((const long long*)lengths)[em]
                                    : (long long)((const int*)lengths)[em];
    __syncthreads();

    unsigned gen = 0;
    uint4 pa[4], pb[4];   // A-chunk prefetch: 4 uint4 per plane per thread

    auto prefetch_h = [&](const __nv_bfloat16* Ah, const __nv_bfloat16* Al, int c) {
#pragma unroll
        for (int i = 0; i < 4; i++) {
            int id = tid + i * NT; int r = id >> 4, cc = id & 15;
            size_t g = (size_t)(m0 + r) * H_ + c * KC2 + cc * 8;
            pa[i] = __ldcg(reinterpret_cast<const uint4*>(Ah + g));
            pb[i] = __ldcg(reinterpret_cast<const uint4*>(Al + g));
        }
    };
    auto prefetch_x = [&](int t) {
#pragma unroll
        for (int i = 0; i < 4; i++) {
            int id = tid + i * NT; int r = id >> 4, cc = id & 15;
            size_t g = (size_t)(m0 + r) * (T_ * I_) + (size_t)t * I_ + cc * 8;
            pa[i] = __ldcg(reinterpret_cast<const uint4*>(xh + g));
            pb[i] = __ldcg(reinterpret_cast<const uint4*>(xl + g));
        }
    };
    auto stores = [&](int buf) {
#pragma unroll
        for (int i = 0; i < 4; i++) {
            int id = tid + i * NT; int r = id >> 4, cc = id & 15;
            *reinterpret_cast<uint4*>(sA + buf * ABUF +        r * LDK + cc * 8) = pa[i];
            *reinterpret_cast<uint4*>(sA + buf * ABUF + 8704 + r * LDK + cc * 8) = pb[i];
        }
    };

    // GEMM over nch chunks of 128 K (chunk 4 = x when nch == 5); result -> sC (2 slabs)
    auto run_gemm = [&](const __nv_bfloat16* Ah, const __nv_bfloat16* Al, int nch, int t) {
        wmma::fragment<wmma::accumulator, 16, 16, 16, float> acc[2][3];
#pragma unroll
        for (int nf = 0; nf < 2; nf++)
#pragma unroll
            for (int p = 0; p < 3; p++) wmma::fill_fragment(acc[nf][p], 0.f);

        prefetch_h(Ah, Al, 0);
        for (int c = 0; c < nch; c++) {
            const int buf = c & 1;
            stores(buf);
            __syncthreads();
            if (c + 1 < nch) {
                if (c + 1 < 4) prefetch_h(Ah, Al, c + 1);
                else           prefetch_x(t);
            }
            const __nv_bfloat16* wH = sW + c * WTILE;
            const __nv_bfloat16* wL = sW + (5 + c) * WTILE;
            const __nv_bfloat16* aBh = sA + buf * ABUF + (wm * 16) * LDK;
            const __nv_bfloat16* aBl = aBh + 8704;
#pragma unroll
            for (int ksl = 0; ksl < 4; ksl++) {
                const int kk = (wk * 4 + ksl) * 16;
                wmma::fragment<wmma::matrix_a, 16, 16, 16, __nv_bfloat16, wmma::row_major> aH, aL;
                wmma::fragment<wmma::matrix_b, 16, 16, 16, __nv_bfloat16, wmma::col_major> bH0, bH1, bL0, bL1;
                wmma::load_matrix_sync(aH,  aBh + kk, LDK);
                wmma::load_matrix_sync(aL,  aBl + kk, LDK);
                wmma::load_matrix_sync(bH0, wH + kk,            LDK);
                wmma::load_matrix_sync(bH1, wH + 16 * LDK + kk, LDK);
                wmma::load_matrix_sync(bL0, wL + kk,            LDK);
                wmma::load_matrix_sync(bL1, wL + 16 * LDK + kk, LDK);
                // 6 independent accumulation chains
                wmma::mma_sync(acc[0][0], aH, bH0, acc[0][0]);
                wmma::mma_sync(acc[1][0], aH, bH1, acc[1][0]);
                wmma::mma_sync(acc[0][1], aH, bL0, acc[0][1]);
                wmma::mma_sync(acc[1][1], aH, bL1, acc[1][1]);
                wmma::mma_sync(acc[0][2], aL, bH0, acc[0][2]);
                wmma::mma_sync(acc[1][2], aL, bH1, acc[1][2]);
            }
        }
        // fold the 3 split-products, park per-K-half partials in sC
#pragma unroll
        for (int nf = 0; nf < 2; nf++) {
#pragma unroll
            for (int e = 0; e < acc[nf][0].num_elements; e++)
                acc[nf][0].x[e] += acc[nf][1].x[e] + acc[nf][2].x[e];
            wmma::store_matrix_sync(sC + wk * 2304 + (wm * 16) * LDC2 + nf * 16,
                                    acc[nf][0], LDC2, wmma::mem_row_major);
        }
        __syncthreads();
    };

    union P { __nv_bfloat16 b[8]; uint4 u; };

    // ---- encoder: 512 serial steps (x @ Wih fused as chunk 4) ----
    for (int t = 0; t < T_; t++) {
        const __nv_bfloat16* Ah = (t & 1) ? g_h1h : g_h0h;
        const __nv_bfloat16* Al = (t & 1) ? g_h1l : g_h0l;
        __nv_bfloat16* Oh = (t & 1) ? g_h0h : g_h1h;
        __nv_bfloat16* Ol = (t & 1) ? g_h0l : g_h1l;
        run_gemm(Ah, Al, 5, t);

        float v[8];
#pragma unroll
        for (int j = 0; j < 8; j++)
            v[j] = sC[er * LDC2 + ec0 + j] + sC[2304 + er * LDC2 + ec0 + j];
        P ph, pl;
        if ((long long)t < mylen) {
#pragma unroll
            for (int j = 0; j < 8; j++) {
                float z = tanhf(v[j] + biasr[j]);
                __nv_bfloat16 hb = __float2bfloat16(z);
                ph.b[j] = hb;
                pl.b[j] = __float2bfloat16(z - __bfloat162float(hb));
            }
        } else {   // frozen row: exact bit copy (L2 reads — addresses recur every 2 steps)
            ph.u = __ldcg(reinterpret_cast<const uint4*>(Ah + (size_t)em * H_ + enb));
            pl.u = __ldcg(reinterpret_cast<const uint4*>(Al + (size_t)em * H_ + enb));
        }
        *reinterpret_cast<uint4*>(Oh + (size_t)em * H_ + enb) = ph.u;
        *reinterpret_cast<uint4*>(Ol + (size_t)em * H_ + enb) = pl.u;
        grid_sync(gen);
    }

    // ---- decoder h-chain: 128 serial steps into nh slab (final h is in h0) ----
    const size_t BH = (size_t)B_ * H_;
    for (int s = 0; s < OT_; s++) {
        const __nv_bfloat16* Ah = (s == 0) ? g_h0h : g_nhh + (size_t)(s - 1) * BH;
        const __nv_bfloat16* Al = (s == 0) ? g_h0l : g_nhl + (size_t)(s - 1) * BH;
        run_gemm(Ah, Al, 4, 0);

        float v[8];
#pragma unroll
        for (int j = 0; j < 8; j++)
            v[j] = sC[er * LDC2 + ec0 + j] + sC[2304 + er * LDC2 + ec0 + j];
        P ph, pl;
#pragma unroll
        for (int j = 0; j < 8; j++) {
            float z = tanhf(v[j] + biasr[j]);
            __nv_bfloat16 hb = __float2bfloat16(z);
            ph.b[j] = hb;
            pl.b[j] = __float2bfloat16(z - __bfloat162float(hb));
        }
        *reinterpret_cast<uint4*>(g_nhh + (size_t)s * BH + (size_t)em * H_ + enb) = ph.u;
        *reinterpret_cast<uint4*>(g_nhl + (size_t)s * BH + (size_t)em * H_ + enb) = pl.u;
        grid_sync(gen);
    }
}

// ---------------- batched FC kernels (parallel; R6-validated) ----------------
// MODE 0: fc1: out = relu(A@fc1W^T + b) -> bf16 hi/lo slab
// MODE 1: fc2: out[b][s][:] = A@fc2W^T + b -> fp32 strided (slab row m -> s = m>>9, b = m&511)
template <int MODE>
__global__ void __launch_bounds__(128)
fc_kernel(const __nv_bfloat16* __restrict__ Ah, const __nv_bfloat16* __restrict__ Al,
          const __nv_bfloat16* __restrict__ Bh, const __nv_bfloat16* __restrict__ Bl,
          const float* __restrict__ bias,
          __nv_bfloat16* __restrict__ outh, __nv_bfloat16* __restrict__ outl,
          float* __restrict__ outf)
{
    __shared__ __align__(16) char smem[27648];
    __nv_bfloat16* sAh = reinterpret_cast<__nv_bfloat16*>(smem);
    __nv_bfloat16* sAl = reinterpret_cast<__nv_bfloat16*>(smem + 9216);
    __nv_bfloat16* sBh = reinterpret_cast<__nv_bfloat16*>(smem + 18432);
    __nv_bfloat16* sBl = reinterpret_cast<__nv_bfloat16*>(smem + 23040);
    float*         sC  = reinterpret_cast<float*>(smem);

    const int tid = threadIdx.x, wid = tid >> 5;
    const int wy = wid >> 1, wx = wid & 1;
    const int m0 = blockIdx.x * 64;
    const int n0 = blockIdx.y * 32;

    wmma::fragment<wmma::accumulator, 16, 16, 16, float> acc0, acc1;
    wmma::fill_fragment(acc0, 0.f);
    wmma::fill_fragment(acc1, 0.f);

    uint4 raH[4], raL[4], rbH[2], rbL[2];
    auto prefetch = [&](int c) {
        const int k0 = c * KC;
#pragma unroll
        for (int i = 0; i < 4; i++) {
            int id = tid + i * 128; int r = id >> 3, cc = id & 7;
            size_t g = (size_t)(m0 + r) * H_ + k0 + cc * 8;
            raH[i] = *reinterpret_cast<const uint4*>(Ah + g);
            raL[i] = *reinterpret_cast<const uint4*>(Al + g);
        }
#pragma unroll
        for (int i = 0; i < 2; i++) {
            int id = tid + i * 128; int r = id >> 3, cc = id & 7;
            size_t g = (size_t)(n0 + r) * H_ + k0 + cc * 8;
            rbH[i] = *reinterpret_cast<const uint4*>(Bh + g);
            rbL[i] = *reinterpret_cast<const uint4*>(Bl + g);
        }
    };
    auto stores = [&]() {
#pragma unroll
        for (int i = 0; i < 4; i++) {
            int id = tid + i * 128; int r = id >> 3, cc = id & 7;
            *reinterpret_cast<uint4*>(sAh + r * LD + cc * 8) = raH[i];
            *reinterpret_cast<uint4*>(sAl + r * LD + cc * 8) = raL[i];
        }
#pragma unroll
        for (int i = 0; i < 2; i++) {
            int id = tid + i * 128; int r = id >> 3, cc = id & 7;
            *reinterpret_cast<uint4*>(sBh + r * LD + cc * 8) = rbH[i];
            *reinterpret_cast<uint4*>(sBl + r * LD + cc * 8) = rbL[i];
        }
    };

    prefetch(0);
    for (int s = 0; s < H_ / KC; s++) {
        stores();
        __syncthreads();
        if (s + 1 < H_ / KC) prefetch(s + 1);
#pragma unroll
        for (int ks = 0; ks < 4; ks++) {
            const int kk = ks * 16;
            wmma::fragment<wmma::matrix_a, 16, 16, 16, __nv_bfloat16, wmma::row_major> aH0, aH1, aL0, aL1;
            wmma::fragment<wmma::matrix_b, 16, 16, 16, __nv_bfloat16, wmma::col_major> bH, bL;
            wmma::load_matrix_sync(aH0, sAh + (wy * 32)      * LD + kk, LD);
            wmma::load_matrix_sync(aH1, sAh + (wy * 32 + 16) * LD + kk, LD);
            wmma::load_matrix_sync(aL0, sAl + (wy * 32)      * LD + kk, LD);
            wmma::load_matrix_sync(aL1, sAl + (wy * 32 + 16) * LD + kk, LD);
            wmma::load_matrix_sync(bH,  sBh + (wx * 16) * LD + kk, LD);
            wmma::load_matrix_sync(bL,  sBl + (wx * 16) * LD + kk, LD);
            wmma::mma_sync(acc0, aH0, bH, acc0);
            wmma::mma_sync(acc1, aH1, bH, acc1);
            wmma::mma_sync(acc0, aH0, bL, acc0);
            wmma::mma_sync(acc1, aH1, bL, acc1);
            wmma::mma_sync(acc0, aL0, bH, acc0);
            wmma::mma_sync(acc1, aL1, bH, acc1);
        }
        __syncthreads();
    }

    wmma::store_matrix_sync(sC + (wy * 32)      * LDC + wx * 16, acc0, LDC, wmma::mem_row_major);
    wmma::store_matrix_sync(sC + (wy * 32 + 16) * LDC + wx * 16, acc1, LDC, wmma::mem_row_major);
    __syncthreads();

    const int r  = tid >> 1;
    const int c0 = (tid & 1) * 16;
    const int m  = m0 + r;
    const int nb = n0 + c0;

    float v[16];
#pragma unroll
    for (int j = 0; j < 4; j++)
        *reinterpret_cast<float4*>(v + j * 4) =
            *reinterpret_cast<const float4*>(sC + r * LDC + c0 + j * 4);

    if constexpr (MODE == 0) {
        union P8 { __nv_bfloat16 b[8]; uint4 u; } ph[2], pl[2];
#pragma unroll
        for (int j = 0; j < 16; j++) {
            float z = fmaxf(v[j] + bias[nb + j], 0.f);
            __nv_bfloat16 hb = __float2bfloat16(z);
            ph[j >> 3].b[j & 7] = hb;
            pl[j >> 3].b[j & 7] = __float2bfloat16(z - __bfloat162float(hb));
        }
        __nv_bfloat16* oh = outh + (size_t)m * H_ + nb;
        __nv_bfloat16* ol = outl + (size_t)m * H_ + nb;
        reinterpret_cast<uint4*>(oh)[0] = ph[0].u; reinterpret_cast<uint4*>(oh)[1] = ph[1].u;
        reinterpret_cast<uint4*>(ol)[0] = pl[0].u; reinterpret_cast<uint4*>(ol)[1] = pl[1].u;
    } else {
        const int s = m >> 9;
        const int b = m & 511;
        float* op = outf + ((size_t)b * OT_ + s) * C_ + nb;
#pragma unroll
        for (int j = 0; j < 16; j++) v[j] += bias[nb + j];
#pragma unroll
        for (int j = 0; j < 4; j++)
            *reinterpret_cast<float4*>(op + j * 4) = *reinterpret_cast<const float4*>(v + j * 4);
    }
}

// ---------------- host ----------------
extern "C" void kernel_launch(void* const* d_in, const int* in_sizes, int n_in,
                              void* d_out, int out_size) {
    const float* x       = (const float*)d_in[0];
    const void*  lengths = d_in[1];
    const float* W_ih = (const float*)d_in[3];
    const float* W_hh = (const float*)d_in[4];
    const float* b_ih = (const float*)d_in[5];
    const float* b_hh = (const float*)d_in[6];
    const float* fc1W = (const float*)d_in[7];
    const float* fc1b = (const float*)d_in[8];
    const float* fc2W = (const float*)d_in[9];
    const float* fc2b = (const float*)d_in[10];
    float* out = (float*)d_out;

    __nv_bfloat16 *xh, *xl, *WhhH, *WhhL, *WihH, *WihL, *f1H, *f1L, *f2H, *f2L, *nhh, *nhl, *mh, *ml;
    cudaGetSymbolAddress((void**)&xh,   g_xh);    cudaGetSymbolAddress((void**)&xl,   g_xl);
    cudaGetSymbolAddress((void**)&WhhH, g_Whh_h); cudaGetSymbolAddress((void**)&WhhL, g_Whh_l);
    cudaGetSymbolAddress((void**)&WihH, g_Wih_h); cudaGetSymbolAddress((void**)&WihL, g_Wih_l);
    cudaGetSymbolAddress((void**)&f1H,  g_f1_h);  cudaGetSymbolAddress((void**)&f1L,  g_f1_l);
    cudaGetSymbolAddress((void**)&f2H,  g_f2_h);  cudaGetSymbolAddress((void**)&f2L,  g_f2_l);
    cudaGetSymbolAddress((void**)&nhh,  g_nhh);   cudaGetSymbolAddress((void**)&nhl,  g_nhl);
    cudaGetSymbolAddress((void**)&mh,   g_mh);    cudaGetSymbolAddress((void**)&ml,   g_ml);

    auto launch_split = [](const float* s, __nv_bfloat16* h, __nv_bfloat16* l, long n) {
        long n4 = n / 4;
        split_kernel<<<(unsigned)((n4 + 255) / 256), 256>>>(s, h, l, n4);
    };
    launch_split(x,    xh,   xl,   (long)B_ * T_ * I_);
    launch_split(W_hh, WhhH, WhhL, (long)H_ * H_);
    launch_split(W_ih, WihH, WihL, (long)H_ * I_);
    launch_split(fc1W, f1H,  f1L,  (long)H_ * H_);
    launch_split(fc2W, f2H,  f2L,  (long)C_ * H_);
    init_kernel<<<(B_ * H_ + 255) / 256, 256>>>(b_ih, b_hh);
    detect_len_kernel<<<1, 1>>>((const int*)lengths);

    // whole serial chain in ONE persistent kernel
    cudaFuncSetAttribute(rnn_persistent, cudaFuncAttributeMaxDynamicSharedMemorySize, SMEM_PERS);
    rnn_persistent<<<dim3(GX, GY), NT, SMEM_PERS>>>(xh, xl, lengths);

    // batched fc1 / fc2 over all (s, b): M = OT*B = 65536
    fc_kernel<0><<<dim3(OT_ * B_ / 64, H_ / 32), 128>>>(nhh, nhl, f1H, f1L, fc1b, mh, ml, nullptr);
    fc_kernel<1><<<dim3(OT_ * B_ / 64, C_ / 32), 128>>>(mh, ml, f2H, f2L, fc2b, nullptr, nullptr, out);
}

// round 11
// speedup vs baseline: 1.4263x; 1.3237x over previous
#include <cuda_runtime.h>
#include <cuda_fp16.h>
#include <mma.h>
#include <cstdint>

using namespace nvcuda;

#define B_  512
#define T_  512
#define I_  128
#define H_  512
#define C_  128
#define OT_ 128

// persistent kernel: grid 8x16 = 128 CTAs, CTA tile 64x32, 8 warps = 4 m-frags x 2 K-halves
#define GX    8
#define GY    16
#define NGRP  16          // CTAs per sync group (one group per mx)
#define NT    256
#define KC2   128
#define LDK   136         // padded half leading dim
#define WT    4352        // one 32x136 half weight tile (elements)
#define ABUF  17408       // one A buffer: 2 planes x 64 x 136 (elements)
#define APL   8704        // plane offset inside A buffer (elements)
#define LDC2  36

// fc kernels: CTA 64x32, 4 warps, KC 64
#define KC   64
#define LD   72
#define LDC  36

// ---------------- device globals (allocation-free scratch) ----------------
__device__ __half g_xh[(size_t)B_ * T_ * I_];
__device__ __half g_xl[(size_t)B_ * T_ * I_];
__device__ __half g_Whh16[H_ * H_];
__device__ __half g_Wih16[H_ * I_];
__device__ __half g_f116[H_ * H_];
__device__ __half g_f216[C_ * H_];
__device__ __half g_h0h[B_ * H_], g_h0l[B_ * H_];
__device__ __half g_h1h[B_ * H_], g_h1l[B_ * H_];
__device__ __half g_nhh[(size_t)OT_ * B_ * H_];     // decoder nh slab [s][b][h]
__device__ __half g_nhl[(size_t)OT_ * B_ * H_];
__device__ __half g_mh[(size_t)OT_ * B_ * H_];      // fc1 out slab
__device__ __half g_ml[(size_t)OT_ * B_ * H_];
__device__ float  g_bias2[H_];                      // b_ih + b_hh
__device__ int    g_len64;
__device__ unsigned g_garr[GX * 256];               // group barrier counters, 1KB apart
__device__ unsigned g_ggen[GX * 256];

// ---------------- prologue kernels ----------------
__global__ void split2h_kernel(const float* __restrict__ s, __half* __restrict__ hi,
                               __half* __restrict__ lo, long n4) {
    long i = (long)blockIdx.x * blockDim.x + threadIdx.x;
    if (i >= n4) return;
    float4 v = reinterpret_cast<const float4*>(s)[i];
    union { __half b[4]; uint2 u; } h, l;
    float a[4] = { v.x, v.y, v.z, v.w };
#pragma unroll
    for (int j = 0; j < 4; j++) {
        h.b[j] = __float2half_rn(a[j]);
        l.b[j] = __float2half_rn(a[j] - __half2float(h.b[j]));
    }
    reinterpret_cast<uint2*>(hi)[i] = h.u;
    reinterpret_cast<uint2*>(lo)[i] = l.u;
}

__global__ void convh_kernel(const float* __restrict__ s, __half* __restrict__ d, long n4) {
    long i = (long)blockIdx.x * blockDim.x + threadIdx.x;
    if (i >= n4) return;
    float4 v = reinterpret_cast<const float4*>(s)[i];
    union { __half b[4]; uint2 u; } h;
    h.b[0] = __float2half_rn(v.x); h.b[1] = __float2half_rn(v.y);
    h.b[2] = __float2half_rn(v.z); h.b[3] = __float2half_rn(v.w);
    reinterpret_cast<uint2*>(d)[i] = h.u;
}

__global__ void init_kernel(const float* __restrict__ b_ih, const float* __restrict__ b_hh) {
    int i = blockIdx.x * blockDim.x + threadIdx.x;
    if (i < H_) g_bias2[i] = b_ih[i] + b_hh[i];
    if (i < B_ * H_) { g_h0h[i] = __float2half(0.f); g_h0l[i] = __float2half(0.f); }
    if (i < GX * 256) { g_garr[i] = 0u; g_ggen[i] = 0u; }
}

// lengths dtype sniff: int64 buffers have all odd int32 words == 0 (values < 512)
__global__ void detect_len_kernel(const int* p) {
    int is64 = 1;
    for (int i = 0; i < 32; i++)
        if (p[2 * i + 1] != 0) is64 = 0;
    g_len64 = is64;
}

// ---------------- per-group barrier (16 CTAs sharing one mx) ----------------
__device__ __forceinline__ void group_sync(int grp, unsigned& gen) {
    __syncthreads();
    if (threadIdx.x == 0) {
        __threadfence();
        unsigned* arr = &g_garr[grp * 256];
        unsigned* gg  = &g_ggen[grp * 256];
        if (atomicAdd(arr, 1u) == NGRP - 1) {
            atomicExch(arr, 0u);
            __threadfence();
            atomicAdd(gg, 1u);
        } else {
            while (atomicAdd(gg, 0u) <= gen) __nanosleep(32);
            __threadfence();
        }
    }
    gen++;
    __syncthreads();
}

// ---------------- persistent serial-chain kernel ----------------
// SMEM (bytes):
//   sW : 5 chunks x [32][136] half = 43520   (chunks 0-3: Whh, 4: Wih)
//   sA : 2 buf x 2 plane x [64][136] half = 69632
//   sC : 2 K-half slabs x [64][36] f32 = 18432
#define SMEM_PERS 131584

__global__ void __launch_bounds__(NT, 1) rnn_persistent(
    const __half* __restrict__ xh, const __half* __restrict__ xl,
    const void* __restrict__ lengths)
{
    extern __shared__ __align__(16) char smem[];
    __half* sW = reinterpret_cast<__half*>(smem);
    __half* sA = reinterpret_cast<__half*>(smem + 43520);
    float*  sC = reinterpret_cast<float*>(smem + 113152);

    const int tid = threadIdx.x;
    const int wid = tid >> 5;
    const int wm  = wid & 3;        // m-frag row: 16*wm
    const int wk  = wid >> 2;       // K-half: ks in [wk*4, wk*4+4)
    const int m0  = blockIdx.x * 64;
    const int n0  = blockIdx.y * 32;
    const int grp = blockIdx.x;

    // ---- resident weight tiles (loaded once) ----
    for (int c = 0; c < 4; c++)
#pragma unroll
        for (int i = 0; i < 2; i++) {
            int id = tid + i * NT; int rr = id >> 4, c2 = id & 15;
            *reinterpret_cast<uint4*>(sW + c * WT + rr * LDK + c2 * 8) =
                *reinterpret_cast<const uint4*>(g_Whh16 + (size_t)(n0 + rr) * H_ + c * KC2 + c2 * 8);
        }
#pragma unroll
    for (int i = 0; i < 2; i++) {
        int id = tid + i * NT; int rr = id >> 4, c2 = id & 15;
        *reinterpret_cast<uint4*>(sW + 4 * WT + rr * LDK + c2 * 8) =
            *reinterpret_cast<const uint4*>(g_Wih16 + (size_t)(n0 + rr) * I_ + c2 * 8);
    }

    // epilogue constants: thread -> (row er, 8-col group)
    const int er  = tid >> 2;
    const int ec0 = (tid & 3) * 8;
    const int em  = m0 + er;
    const int enb = n0 + ec0;
    float biasr[8];
#pragma unroll
    for (int j = 0; j < 8; j++) biasr[j] = g_bias2[enb + j];
    const long long mylen = g_len64 ? ((const long long*)lengths)[em]
                                    : (long long)((const int*)lengths)[em];
    __syncthreads();

    unsigned gen = 0;
    uint4 pa[4], pb[4];   // per-chunk prefetch: 4 uint4 per plane per thread

    auto prefetch_h = [&](const __half* Ah, const __half* Al, int c) {
#pragma unroll
        for (int i = 0; i < 4; i++) {
            int id = tid + i * NT; int r = id >> 4, cc = id & 15;
            size_t g = (size_t)(m0 + r) * H_ + c * KC2 + cc * 8;
            pa[i] = __ldcg(reinterpret_cast<const uint4*>(Ah + g));
            pb[i] = __ldcg(reinterpret_cast<const uint4*>(Al + g));
        }
    };
    auto prefetch_x = [&](int t) {
#pragma unroll
        for (int i = 0; i < 4; i++) {
            int id = tid + i * NT; int r = id >> 4, cc = id & 15;
            size_t g = (size_t)(m0 + r) * (T_ * I_) + (size_t)t * I_ + cc * 8;
            pa[i] = __ldcg(reinterpret_cast<const uint4*>(xh + g));
            pb[i] = __ldcg(reinterpret_cast<const uint4*>(xl + g));
        }
    };
    auto stores = [&](int buf) {
#pragma unroll
        for (int i = 0; i < 4; i++) {
            int id = tid + i * NT; int r = id >> 4, cc = id & 15;
            *reinterpret_cast<uint4*>(sA + buf * ABUF +       r * LDK + cc * 8) = pa[i];
            *reinterpret_cast<uint4*>(sA + buf * ABUF + APL + r * LDK + cc * 8) = pb[i];
        }
    };

    // GEMM over nch chunks of 128 K (chunk 4 = x when nch == 5); result -> sC (2 slabs)
    auto run_gemm = [&](const __half* Ah, const __half* Al, int nch, int t) {
        wmma::fragment<wmma::accumulator, 16, 16, 16, float> acc[2][2];
#pragma unroll
        for (int nf = 0; nf < 2; nf++)
#pragma unroll
            for (int p = 0; p < 2; p++) wmma::fill_fragment(acc[nf][p], 0.f);

        prefetch_h(Ah, Al, 0);
        for (int c = 0; c < nch; c++) {
            const int buf = c & 1;
            stores(buf);
            __syncthreads();
            if (c + 1 < nch) {
                if (c + 1 < 4) prefetch_h(Ah, Al, c + 1);
                else           prefetch_x(t);
            }
            const __half* wB  = sW + c * WT;
            const __half* aBh = sA + buf * ABUF + (wm * 16) * LDK;
            const __half* aBl = aBh + APL;
#pragma unroll
            for (int ksl = 0; ksl < 4; ksl++) {
                const int kk = (wk * 4 + ksl) * 16;
                wmma::fragment<wmma::matrix_a, 16, 16, 16, __half, wmma::row_major> aH, aL;
                wmma::fragment<wmma::matrix_b, 16, 16, 16, __half, wmma::col_major> b0, b1;
                wmma::load_matrix_sync(aH, aBh + kk, LDK);
                wmma::load_matrix_sync(aL, aBl + kk, LDK);
                wmma::load_matrix_sync(b0, wB + kk,            LDK);
                wmma::load_matrix_sync(b1, wB + 16 * LDK + kk, LDK);
                // 4 independent accumulation chains
                wmma::mma_sync(acc[0][0], aH, b0, acc[0][0]);
                wmma::mma_sync(acc[1][0], aH, b1, acc[1][0]);
                wmma::mma_sync(acc[0][1], aL, b0, acc[0][1]);
                wmma::mma_sync(acc[1][1], aL, b1, acc[1][1]);
            }
        }
#pragma unroll
        for (int nf = 0; nf < 2; nf++) {
#pragma unroll
            for (int e = 0; e < acc[nf][0].num_elements; e++)
                acc[nf][0].x[e] += acc[nf][1].x[e];
            wmma::store_matrix_sync(sC + wk * 2304 + (wm * 16) * LDC2 + nf * 16,
                                    acc[nf][0], LDC2, wmma::mem_row_major);
        }
        __syncthreads();
    };

    union P { __half b[8]; uint4 u; };

    // ---- encoder: 512 serial steps (x @ Wih fused as chunk 4) ----
    for (int t = 0; t < T_; t++) {
        const __half* Ah = (t & 1) ? g_h1h : g_h0h;
        const __half* Al = (t & 1) ? g_h1l : g_h0l;
        __half* Oh = (t & 1) ? g_h0h : g_h1h;
        __half* Ol = (t & 1) ? g_h0l : g_h1l;
        run_gemm(Ah, Al, 5, t);

        float v[8];
#pragma unroll
        for (int j = 0; j < 8; j++)
            v[j] = sC[er * LDC2 + ec0 + j] + sC[2304 + er * LDC2 + ec0 + j];
        P ph, pl;
        if ((long long)t < mylen) {
#pragma unroll
            for (int j = 0; j < 8; j++) {
                float z = tanhf(v[j] + biasr[j]);
                __half hb = __float2half_rn(z);
                ph.b[j] = hb;
                pl.b[j] = __float2half_rn(z - __half2float(hb));
            }
        } else {   // frozen row: exact bit copy (L2 reads — addresses recur every 2 steps)
            ph.u = __ldcg(reinterpret_cast<const uint4*>(Ah + (size_t)em * H_ + enb));
            pl.u = __ldcg(reinterpret_cast<const uint4*>(Al + (size_t)em * H_ + enb));
        }
        *reinterpret_cast<uint4*>(Oh + (size_t)em * H_ + enb) = ph.u;
        *reinterpret_cast<uint4*>(Ol + (size_t)em * H_ + enb) = pl.u;
        group_sync(grp, gen);
    }

    // ---- decoder h-chain: 128 serial steps into nh slab (final h is in h0) ----
    const size_t BH = (size_t)B_ * H_;
    for (int s = 0; s < OT_; s++) {
        const __half* Ah = (s == 0) ? g_h0h : g_nhh + (size_t)(s - 1) * BH;
        const __half* Al = (s == 0) ? g_h0l : g_nhl + (size_t)(s - 1) * BH;
        run_gemm(Ah, Al, 4, 0);

        float v[8];
#pragma unroll
        for (int j = 0; j < 8; j++)
            v[j] = sC[er * LDC2 + ec0 + j] + sC[2304 + er * LDC2 + ec0 + j];
        P ph, pl;
#pragma unroll
        for (int j = 0; j < 8; j++) {
            float z = tanhf(v[j] + biasr[j]);
            __half hb = __float2half_rn(z);
            ph.b[j] = hb;
            pl.b[j] = __float2half_rn(z - __half2float(hb));
        }
        *reinterpret_cast<uint4*>(g_nhh + (size_t)s * BH + (size_t)em * H_ + enb) = ph.u;
        *reinterpret_cast<uint4*>(g_nhl + (size_t)s * BH + (size_t)em * H_ + enb) = pl.u;
        group_sync(grp, gen);
    }
}

// ---------------- batched FC kernels (parallel; fp16 2-product) ----------------
// MODE 0: fc1: out = relu(A@fc1W^T + b) -> half hi/lo slab
// MODE 1: fc2: out[b][s][:] = A@fc2W^T + b -> fp32 strided (slab row m -> s = m>>9, b = m&511)
template <int MODE>
__global__ void __launch_bounds__(128)
fc_kernel(const __half* __restrict__ Ah, const __half* __restrict__ Al,
          const __half* __restrict__ Bw,
          const float* __restrict__ bias,
          __half* __restrict__ outh, __half* __restrict__ outl,
          float* __restrict__ outf)
{
    __shared__ __align__(16) char smem[23040];
    __half* sAh = reinterpret_cast<__half*>(smem);            // 9216 B
    __half* sAl = reinterpret_cast<__half*>(smem + 9216);     // 9216 B
    __half* sB  = reinterpret_cast<__half*>(smem + 18432);    // 4608 B
    float*  sC  = reinterpret_cast<float*>(smem);             // reuse after mma

    const int tid = threadIdx.x, wid = tid >> 5;
    const int wy = wid >> 1, wx = wid & 1;
    const int m0 = blockIdx.x * 64;
    const int n0 = blockIdx.y * 32;

    wmma::fragment<wmma::accumulator, 16, 16, 16, float> acc00, acc01, acc10, acc11;
    wmma::fill_fragment(acc00, 0.f);
    wmma::fill_fragment(acc01, 0.f);
    wmma::fill_fragment(acc10, 0.f);
    wmma::fill_fragment(acc11, 0.f);

    uint4 raH[4], raL[4], rb[2];
    auto prefetch = [&](int c) {
        const int k0 = c * KC;
#pragma unroll
        for (int i = 0; i < 4; i++) {
            int id = tid + i * 128; int r = id >> 3, cc = id & 7;
            size_t g = (size_t)(m0 + r) * H_ + k0 + cc * 8;
            raH[i] = *reinterpret_cast<const uint4*>(Ah + g);
            raL[i] = *reinterpret_cast<const uint4*>(Al + g);
        }
#pragma unroll
        for (int i = 0; i < 2; i++) {
            int id = tid + i * 128; int r = id >> 3, cc = id & 7;
            rb[i] = *reinterpret_cast<const uint4*>(Bw + (size_t)(n0 + r) * H_ + k0 + cc * 8);
        }
    };
    auto stores = [&]() {
#pragma unroll
        for (int i = 0; i < 4; i++) {
            int id = tid + i * 128; int r = id >> 3, cc = id & 7;
            *reinterpret_cast<uint4*>(sAh + r * LD + cc * 8) = raH[i];
            *reinterpret_cast<uint4*>(sAl + r * LD + cc * 8) = raL[i];
        }
#pragma unroll
        for (int i = 0; i < 2; i++) {
            int id = tid + i * 128; int r = id >> 3, cc = id & 7;
            *reinterpret_cast<uint4*>(sB + r * LD + cc * 8) = rb[i];
        }
    };

    prefetch(0);
    for (int s = 0; s < H_ / KC; s++) {
        stores();
        __syncthreads();
        if (s + 1 < H_ / KC) prefetch(s + 1);
#pragma unroll
        for (int ks = 0; ks < 4; ks++) {
            const int kk = ks * 16;
            wmma::fragment<wmma::matrix_a, 16, 16, 16, __half, wmma::row_major> aH0, aH1, aL0, aL1;
            wmma::fragment<wmma::matrix_b, 16, 16, 16, __half, wmma::col_major> b;
            wmma::load_matrix_sync(aH0, sAh + (wy * 32)      * LD + kk, LD);
            wmma::load_matrix_sync(aH1, sAh + (wy * 32 + 16) * LD + kk, LD);
            wmma::load_matrix_sync(aL0, sAl + (wy * 32)      * LD + kk, LD);
            wmma::load_matrix_sync(aL1, sAl + (wy * 32 + 16) * LD + kk, LD);
            wmma::load_matrix_sync(b,   sB  + (wx * 16) * LD + kk, LD);
            wmma::mma_sync(acc00, aH0, b, acc00);
            wmma::mma_sync(acc10, aH1, b, acc10);
            wmma::mma_sync(acc01, aL0, b, acc01);
            wmma::mma_sync(acc11, aL1, b, acc11);
        }
        __syncthreads();
    }

#pragma unroll
    for (int e = 0; e < acc00.num_elements; e++) {
        acc00.x[e] += acc01.x[e];
        acc10.x[e] += acc11.x[e];
    }
    wmma::store_matrix_sync(sC + (wy * 32)      * LDC + wx * 16, acc00, LDC, wmma::mem_row_major);
    wmma::store_matrix_sync(sC + (wy * 32 + 16) * LDC + wx * 16, acc10, LDC, wmma::mem_row_major);
    __syncthreads();

    const int r  = tid >> 1;
    const int c0 = (tid & 1) * 16;
    const int m  = m0 + r;
    const int nb = n0 + c0;

    float v[16];
#pragma unroll
    for (int j = 0; j < 4; j++)
        *reinterpret_cast<float4*>(v + j * 4) =
            *reinterpret_cast<const float4*>(sC + r * LDC + c0 + j * 4);

    if constexpr (MODE == 0) {
        union P8 { __half b[8]; uint4 u; } ph[2], pl[2];
#pragma unroll
        for (int j = 0; j < 16; j++) {
            float z = fmaxf(v[j] + bias[nb + j], 0.f);
            __half hb = __float2half_rn(z);
            ph[j >> 3].b[j & 7] = hb;
            pl[j >> 3].b[j & 7] = __float2half_rn(z - __half2float(hb));
        }
        __half* oh = outh + (size_t)m * H_ + nb;
        __half* ol = outl + (size_t)m * H_ + nb;
        reinterpret_cast<uint4*>(oh)[0] = ph[0].u; reinterpret_cast<uint4*>(oh)[1] = ph[1].u;
        reinterpret_cast<uint4*>(ol)[0] = pl[0].u; reinterpret_cast<uint4*>(ol)[1] = pl[1].u;
    } else {
        const int s = m >> 9;
        const int b = m & 511;
        float* op = outf + ((size_t)b * OT_ + s) * C_ + nb;
#pragma unroll
        for (int j = 0; j < 16; j++) v[j] += bias[nb + j];
#pragma unroll
        for (int j = 0; j < 4; j++)
            *reinterpret_cast<float4*>(op + j * 4) = *reinterpret_cast<const float4*>(v + j * 4);
    }
}

// ---------------- host ----------------
extern "C" void kernel_launch(void* const* d_in, const int* in_sizes, int n_in,
                              void* d_out, int out_size) {
    const float* x       = (const float*)d_in[0];
    const void*  lengths = d_in[1];
    const float* W_ih = (const float*)d_in[3];
    const float* W_hh = (const float*)d_in[4];
    const float* b_ih = (const float*)d_in[5];
    const float* b_hh = (const float*)d_in[6];
    const float* fc1W = (const float*)d_in[7];
    const float* fc1b = (const float*)d_in[8];
    const float* fc2W = (const float*)d_in[9];
    const float* fc2b = (const float*)d_in[10];
    float* out = (float*)d_out;

    __half *xh, *xl, *Whh16, *Wih16, *f116, *f216, *nhh, *nhl, *mh, *ml;
    cudaGetSymbolAddress((void**)&xh,    g_xh);    cudaGetSymbolAddress((void**)&xl,    g_xl);
    cudaGetSymbolAddress((void**)&Whh16, g_Whh16); cudaGetSymbolAddress((void**)&Wih16, g_Wih16);
    cudaGetSymbolAddress((void**)&f116,  g_f116);  cudaGetSymbolAddress((void**)&f216,  g_f216);
    cudaGetSymbolAddress((void**)&nhh,   g_nhh);   cudaGetSymbolAddress((void**)&nhl,   g_nhl);
    cudaGetSymbolAddress((void**)&mh,    g_mh);    cudaGetSymbolAddress((void**)&ml,    g_ml);

    // prologue: x -> fp16 hi/lo split; weights -> fp16; bias2; h0 = 0; barrier reset
    long nx4 = (long)B_ * T_ * I_ / 4;
    split2h_kernel<<<(unsigned)((nx4 + 255) / 256), 256>>>(x, xh, xl, nx4);
    convh_kernel<<<(H_ * H_ / 4 + 255) / 256, 256>>>(W_hh, Whh16, H_ * H_ / 4);
    convh_kernel<<<(H_ * I_ / 4 + 255) / 256, 256>>>(W_ih, Wih16, H_ * I_ / 4);
    convh_kernel<<<(H_ * H_ / 4 + 255) / 256, 256>>>(fc1W, f116, H_ * H_ / 4);
    convh_kernel<<<(C_ * H_ / 4 + 255) / 256, 256>>>(fc2W, f216, C_ * H_ / 4);
    init_kernel<<<(B_ * H_ + 255) / 256, 256>>>(b_ih, b_hh);
    detect_len_kernel<<<1, 1>>>((const int*)lengths);

    // whole serial chain in ONE persistent kernel
    cudaFuncSetAttribute(rnn_persistent, cudaFuncAttributeMaxDynamicSharedMemorySize, SMEM_PERS);
    rnn_persistent<<<dim3(GX, GY), NT, SMEM_PERS>>>(xh, xl, lengths);

    // batched fc1 / fc2 over all (s, b): M = OT*B = 65536
    fc_kernel<0><<<dim3(OT_ * B_ / 64, H_ / 32), 128>>>(nhh, nhl, f116, fc1b, mh, ml, nullptr);
    fc_kernel<1><<<dim3(OT_ * B_ / 64, C_ / 32), 128>>>(mh, ml, f216, fc2b, nullptr, nullptr, out);
}

// round 12
// speedup vs baseline: 1.8429x; 1.2921x over previous
#include <cuda_runtime.h>
#include <cuda_fp16.h>
#include <mma.h>
#include <cstdint>

using namespace nvcuda;

#define B_  512
#define T_  512
#define I_  128
#define H_  512
#define C_  128
#define OT_ 128

// persistent kernel: grid 8x16 = 128 CTAs, CTA tile 64x32, 8 warps = 4 m-frags x 2 K-halves
#define GX    8
#define GY    16
#define NGRP  16          // CTAs per sync group (one group per mx)
#define NT    256
#define LDA   648         // unified K layout: h cols 0-511, x cols 512-639 (+8 pad)
#define LDC2  36

// fc kernels: CTA 64x32, 4 warps, KC 64
#define KC   64
#define LD   72
#define LDC  36

// ---------------- device globals (allocation-free scratch) ----------------
__device__ __half g_x16[(size_t)B_ * T_ * I_];
__device__ __half g_Whh16[H_ * H_];
__device__ __half g_Wih16[H_ * I_];
__device__ __half g_f116[H_ * H_];
__device__ __half g_f216[C_ * H_];
__device__ __half g_h0h[B_ * H_], g_h1h[B_ * H_];   // single-plane hidden, ping-pong
__device__ __half g_nhh[(size_t)OT_ * B_ * H_];     // decoder nh hi (GEMM + fc)
__device__ __half g_nhl[(size_t)OT_ * B_ * H_];     // decoder nh lo (fc precision)
__device__ __half g_mh[(size_t)OT_ * B_ * H_];      // fc1 out hi
__device__ __half g_ml[(size_t)OT_ * B_ * H_];      // fc1 out lo
__device__ float  g_bias2[H_];                      // b_ih + b_hh
__device__ int    g_len64;
__device__ unsigned g_garr[GX * 256];               // group barrier counters, 1KB apart
__device__ unsigned g_ggen[GX * 256];

// ---------------- prologue kernels ----------------
__global__ void convh_kernel(const float* __restrict__ s, __half* __restrict__ d, long n4) {
    long i = (long)blockIdx.x * blockDim.x + threadIdx.x;
    if (i >= n4) return;
    float4 v = reinterpret_cast<const float4*>(s)[i];
    union { __half b[4]; uint2 u; } h;
    h.b[0] = __float2half_rn(v.x); h.b[1] = __float2half_rn(v.y);
    h.b[2] = __float2half_rn(v.z); h.b[3] = __float2half_rn(v.w);
    reinterpret_cast<uint2*>(d)[i] = h.u;
}

__global__ void init_kernel(const float* __restrict__ b_ih, const float* __restrict__ b_hh) {
    int i = blockIdx.x * blockDim.x + threadIdx.x;
    if (i < H_) g_bias2[i] = b_ih[i] + b_hh[i];
    if (i < B_ * H_) g_h0h[i] = __float2half(0.f);
    if (i < GX * 256) { g_garr[i] = 0u; g_ggen[i] = 0u; }
}

// lengths dtype sniff: int64 buffers have all odd int32 words == 0 (values < 512)
__global__ void detect_len_kernel(const int* p) {
    int is64 = 1;
    for (int i = 0; i < 32; i++)
        if (p[2 * i + 1] != 0) is64 = 0;
    g_len64 = is64;
}

// ---------------- per-group barrier (16 CTAs sharing one mx) ----------------
__device__ __forceinline__ void group_sync(int grp, unsigned& gen) {
    __syncthreads();
    if (threadIdx.x == 0) {
        __threadfence();
        unsigned* arr = &g_garr[grp * 256];
        unsigned* gg  = &g_ggen[grp * 256];
        if (atomicAdd(arr, 1u) == NGRP - 1) {
            atomicExch(arr, 0u);
            __threadfence();
            atomicAdd(gg, 1u);
        } else {
            while (atomicAdd(gg, 0u) <= gen) __nanosleep(32);
            __threadfence();
        }
    }
    gen++;
    __syncthreads();
}

// ---------------- persistent serial-chain kernel ----------------
// SMEM (bytes), single-plane fp16:
//   sW : [32][648] half = 41472   (cols 0-511: Whh, 512-639: Wih, unified K)
//   sA : [64][648] half = 82944   (cols 0-511: h,   512-639: x_t)
//   sC : 2 K-half slabs x [64][36] f32 = 18432
#define SW_OFF 0
#define SA_OFF 41472
#define SC_OFF 124416
#define SMEM_PERS 142848

__global__ void __launch_bounds__(NT, 1) rnn_persistent(
    const __half* __restrict__ x16, const void* __restrict__ lengths)
{
    extern __shared__ __align__(16) char smem[];
    __half* sW = reinterpret_cast<__half*>(smem + SW_OFF);
    __half* sA = reinterpret_cast<__half*>(smem + SA_OFF);
    float*  sC = reinterpret_cast<float*>(smem + SC_OFF);

    const int tid = threadIdx.x;
    const int wid = tid >> 5;
    const int wm  = wid & 3;        // m-frag row: 16*wm
    const int wk  = wid >> 2;       // K-half
    const int m0  = blockIdx.x * 64;
    const int n0  = blockIdx.y * 32;
    const int grp = blockIdx.x;

    // ---- resident weight tile (loaded once): rows n, unified K cols ----
#pragma unroll
    for (int i = 0; i < 8; i++) {                    // Whh: 32 x 512 -> cols 0-511
        int id = tid + i * NT; int r = id >> 6, c = id & 63;
        *reinterpret_cast<uint4*>(sW + r * LDA + c * 8) =
            *reinterpret_cast<const uint4*>(g_Whh16 + (size_t)(n0 + r) * H_ + c * 8);
    }
#pragma unroll
    for (int i = 0; i < 2; i++) {                    // Wih: 32 x 128 -> cols 512-639
        int id = tid + i * NT; int r = id >> 4, c = id & 15;
        *reinterpret_cast<uint4*>(sW + r * LDA + 512 + c * 8) =
            *reinterpret_cast<const uint4*>(g_Wih16 + (size_t)(n0 + r) * I_ + c * 8);
    }

    // epilogue constants: thread -> (row er, 8-col group)
    const int er  = tid >> 2;
    const int ec0 = (tid & 3) * 8;
    const int em  = m0 + er;
    const int enb = n0 + ec0;
    float biasr[8];
#pragma unroll
    for (int j = 0; j < 8; j++) biasr[j] = g_bias2[enb + j];
    const long long mylen = g_len64 ? ((const long long*)lengths)[em]
                                    : (long long)((const int*)lengths)[em];
    __syncthreads();

    unsigned gen = 0;

    // load A slab (h, optionally x_t), ONE barrier, full-K MMA, fold into sC
    auto run_gemm = [&](const __half* __restrict__ Asrc, int t, bool withx, int nks) {
#pragma unroll
        for (int i = 0; i < 16; i++) {               // h: 64 x 512
            int id = tid + i * NT; int r = id >> 6, c = id & 63;
            *reinterpret_cast<uint4*>(sA + r * LDA + c * 8) =
                __ldcg(reinterpret_cast<const uint4*>(Asrc + (size_t)(m0 + r) * H_ + c * 8));
        }
        if (withx) {
#pragma unroll
            for (int i = 0; i < 4; i++) {            // x_t: 64 x 128 -> cols 512-639
                int id = tid + i * NT; int r = id >> 4, c = id & 15;
                *reinterpret_cast<uint4*>(sA + r * LDA + 512 + c * 8) =
                    __ldcg(reinterpret_cast<const uint4*>(
                        x16 + (size_t)(m0 + r) * (T_ * I_) + (size_t)t * I_ + c * 8));
            }
        }
        __syncthreads();

        wmma::fragment<wmma::accumulator, 16, 16, 16, float> acc[2][2];
#pragma unroll
        for (int nf = 0; nf < 2; nf++)
#pragma unroll
            for (int p = 0; p < 2; p++) wmma::fill_fragment(acc[nf][p], 0.f);

        const int ks0 = wk * (nks >> 1);
        const int ks1 = ks0 + (nks >> 1);
        const __half* aB = sA + (wm * 16) * LDA;
#pragma unroll 4
        for (int ks = ks0; ks < ks1; ks++) {
            const int kk = ks * 16;
            wmma::fragment<wmma::matrix_a, 16, 16, 16, __half, wmma::row_major> a;
            wmma::fragment<wmma::matrix_b, 16, 16, 16, __half, wmma::col_major> b0, b1;
            wmma::load_matrix_sync(a,  aB + kk, LDA);
            wmma::load_matrix_sync(b0, sW + kk,            LDA);
            wmma::load_matrix_sync(b1, sW + 16 * LDA + kk, LDA);
            const int p = ks & 1;                    // 4 independent chains
            wmma::mma_sync(acc[0][p], a, b0, acc[0][p]);
            wmma::mma_sync(acc[1][p], a, b1, acc[1][p]);
        }
#pragma unroll
        for (int nf = 0; nf < 2; nf++) {
#pragma unroll
            for (int e = 0; e < acc[nf][0].num_elements; e++)
                acc[nf][0].x[e] += acc[nf][1].x[e];
            wmma::store_matrix_sync(sC + wk * 2304 + (wm * 16) * LDC2 + nf * 16,
                                    acc[nf][0], LDC2, wmma::mem_row_major);
        }
        __syncthreads();
    };

    union P { __half b[8]; uint4 u; };

    // ---- encoder: 512 serial steps (x @ Wih fused via unified K cols 512-639) ----
    for (int t = 0; t < T_; t++) {
        const __half* Ah = (t & 1) ? g_h1h : g_h0h;
        __half*       Oh = (t & 1) ? g_h0h : g_h1h;
        run_gemm(Ah, t, true, 40);

        float v[8];
#pragma unroll
        for (int j = 0; j < 8; j++)
            v[j] = sC[er * LDC2 + ec0 + j] + sC[2304 + er * LDC2 + ec0 + j];
        P ph;
        if ((long long)t < mylen) {
#pragma unroll
            for (int j = 0; j < 8; j++)
                ph.b[j] = __float2half_rn(tanhf(v[j] + biasr[j]));
        } else {   // frozen row: exact bit copy (L2 read — addresses recur every 2 steps)
            ph.u = __ldcg(reinterpret_cast<const uint4*>(Ah + (size_t)em * H_ + enb));
        }
        *reinterpret_cast<uint4*>(Oh + (size_t)em * H_ + enb) = ph.u;
        group_sync(grp, gen);
    }

    // ---- decoder h-chain: 128 serial steps into nh slab (final h in g_h0h) ----
    const size_t BH = (size_t)B_ * H_;
    for (int s = 0; s < OT_; s++) {
        const __half* Ah = (s == 0) ? g_h0h : g_nhh + (size_t)(s - 1) * BH;
        run_gemm(Ah, 0, false, 32);

        float v[8];
#pragma unroll
        for (int j = 0; j < 8; j++)
            v[j] = sC[er * LDC2 + ec0 + j] + sC[2304 + er * LDC2 + ec0 + j];
        P ph, pl;
#pragma unroll
        for (int j = 0; j < 8; j++) {
            float z = tanhf(v[j] + biasr[j]);
            __half hb = __float2half_rn(z);
            ph.b[j] = hb;
            pl.b[j] = __float2half_rn(z - __half2float(hb));   // lo plane for fc precision
        }
        *reinterpret_cast<uint4*>(g_nhh + (size_t)s * BH + (size_t)em * H_ + enb) = ph.u;
        *reinterpret_cast<uint4*>(g_nhl + (size_t)s * BH + (size_t)em * H_ + enb) = pl.u;
        group_sync(grp, gen);
    }
}

// ---------------- batched FC kernels (parallel; A 2-plane, W fp16) ----------------
// MODE 0: fc1: out = relu(A@fc1W^T + b) -> half hi/lo slab
// MODE 1: fc2: out[b][s][:] = A@fc2W^T + b -> fp32 strided (slab row m -> s = m>>9, b = m&511)
template <int MODE>
__global__ void __launch_bounds__(128)
fc_kernel(const __half* __restrict__ Ah, const __half* __restrict__ Al,
          const __half* __restrict__ Bw,
          const float* __restrict__ bias,
          __half* __restrict__ outh, __half* __restrict__ outl,
          float* __restrict__ outf)
{
    __shared__ __align__(16) char smem[23040];
    __half* sAh = reinterpret_cast<__half*>(smem);            // 9216 B
    __half* sAl = reinterpret_cast<__half*>(smem + 9216);     // 9216 B
    __half* sB  = reinterpret_cast<__half*>(smem + 18432);    // 4608 B
    float*  sC  = reinterpret_cast<float*>(smem);             // reuse after mma

    const int tid = threadIdx.x, wid = tid >> 5;
    const int wy = wid >> 1, wx = wid & 1;
    const int m0 = blockIdx.x * 64;
    const int n0 = blockIdx.y * 32;

    wmma::fragment<wmma::accumulator, 16, 16, 16, float> acc00, acc01, acc10, acc11;
    wmma::fill_fragment(acc00, 0.f);
    wmma::fill_fragment(acc01, 0.f);
    wmma::fill_fragment(acc10, 0.f);
    wmma::fill_fragment(acc11, 0.f);

    uint4 raH[4], raL[4], rb[2];
    auto prefetch = [&](int c) {
        const int k0 = c * KC;
#pragma unroll
        for (int i = 0; i < 4; i++) {
            int id = tid + i * 128; int r = id >> 3, cc = id & 7;
            size_t g = (size_t)(m0 + r) * H_ + k0 + cc * 8;
            raH[i] = *reinterpret_cast<const uint4*>(Ah + g);
            raL[i] = *reinterpret_cast<const uint4*>(Al + g);
        }
#pragma unroll
        for (int i = 0; i < 2; i++) {
            int id = tid + i * 128; int r = id >> 3, cc = id & 7;
            rb[i] = *reinterpret_cast<const uint4*>(Bw + (size_t)(n0 + r) * H_ + k0 + cc * 8);
        }
    };
    auto stores = [&]() {
#pragma unroll
        for (int i = 0; i < 4; i++) {
            int id = tid + i * 128; int r = id >> 3, cc = id & 7;
            *reinterpret_cast<uint4*>(sAh + r * LD + cc * 8) = raH[i];
            *reinterpret_cast<uint4*>(sAl + r * LD + cc * 8) = raL[i];
        }
#pragma unroll
        for (int i = 0; i < 2; i++) {
            int id = tid + i * 128; int r = id >> 3, cc = id & 7;
            *reinterpret_cast<uint4*>(sB + r * LD + cc * 8) = rb[i];
        }
    };

    prefetch(0);
    for (int s = 0; s < H_ / KC; s++) {
        stores();
        __syncthreads();
        if (s + 1 < H_ / KC) prefetch(s + 1);
#pragma unroll
        for (int ks = 0; ks < 4; ks++) {
            const int kk = ks * 16;
            wmma::fragment<wmma::matrix_a, 16, 16, 16, __half, wmma::row_major> aH0, aH1, aL0, aL1;
            wmma::fragment<wmma::matrix_b, 16, 16, 16, __half, wmma::col_major> b;
            wmma::load_matrix_sync(aH0, sAh + (wy * 32)      * LD + kk, LD);
            wmma::load_matrix_sync(aH1, sAh + (wy * 32 + 16) * LD + kk, LD);
            wmma::load_matrix_sync(aL0, sAl + (wy * 32)      * LD + kk, LD);
            wmma::load_matrix_sync(aL1, sAl + (wy * 32 + 16) * LD + kk, LD);
            wmma::load_matrix_sync(b,   sB  + (wx * 16) * LD + kk, LD);
            wmma::mma_sync(acc00, aH0, b, acc00);
            wmma::mma_sync(acc10, aH1, b, acc10);
            wmma::mma_sync(acc01, aL0, b, acc01);
            wmma::mma_sync(acc11, aL1, b, acc11);
        }
        __syncthreads();
    }

#pragma unroll
    for (int e = 0; e < acc00.num_elements; e++) {
        acc00.x[e] += acc01.x[e];
        acc10.x[e] += acc11.x[e];
    }
    wmma::store_matrix_sync(sC + (wy * 32)      * LDC + wx * 16, acc00, LDC, wmma::mem_row_major);
    wmma::store_matrix_sync(sC + (wy * 32 + 16) * LDC + wx * 16, acc10, LDC, wmma::mem_row_major);
    __syncthreads();

    const int r  = tid >> 1;
    const int c0 = (tid & 1) * 16;
    const int m  = m0 + r;
    const int nb = n0 + c0;

    float v[16];
#pragma unroll
    for (int j = 0; j < 4; j++)
        *reinterpret_cast<float4*>(v + j * 4) =
            *reinterpret_cast<const float4*>(sC + r * LDC + c0 + j * 4);

    if constexpr (MODE == 0) {
        union P8 { __half b[8]; uint4 u; } ph[2], pl[2];
#pragma unroll
        for (int j = 0; j < 16; j++) {
            float z = fmaxf(v[j] + bias[nb + j], 0.f);
            __half hb = __float2half_rn(z);
            ph[j >> 3].b[j & 7] = hb;
            pl[j >> 3].b[j & 7] = __float2half_rn(z - __half2float(hb));
        }
        __half* oh = outh + (size_t)m * H_ + nb;
        __half* ol = outl + (size_t)m * H_ + nb;
        reinterpret_cast<uint4*>(oh)[0] = ph[0].u; reinterpret_cast<uint4*>(oh)[1] = ph[1].u;
        reinterpret_cast<uint4*>(ol)[0] = pl[0].u; reinterpret_cast<uint4*>(ol)[1] = pl[1].u;
    } else {
        const int s = m >> 9;
        const int b = m & 511;
        float* op = outf + ((size_t)b * OT_ + s) * C_ + nb;
#pragma unroll
        for (int j = 0; j < 16; j++) v[j] += bias[nb + j];
#pragma unroll
        for (int j = 0; j < 4; j++)
            *reinterpret_cast<float4*>(op + j * 4) = *reinterpret_cast<const float4*>(v + j * 4);
    }
}

// ---------------- host ----------------
extern "C" void kernel_launch(void* const* d_in, const int* in_sizes, int n_in,
                              void* d_out, int out_size) {
    const float* x       = (const float*)d_in[0];
    const void*  lengths = d_in[1];
    const float* W_ih = (const float*)d_in[3];
    const float* W_hh = (const float*)d_in[4];
    const float* b_ih = (const float*)d_in[5];
    const float* b_hh = (const float*)d_in[6];
    const float* fc1W = (const float*)d_in[7];
    const float* fc1b = (const float*)d_in[8];
    const float* fc2W = (const float*)d_in[9];
    const float* fc2b = (const float*)d_in[10];
    float* out = (float*)d_out;

    __half *x16, *Whh16, *Wih16, *f116, *f216, *nhh, *nhl, *mh, *ml;
    cudaGetSymbolAddress((void**)&x16,   g_x16);
    cudaGetSymbolAddress((void**)&Whh16, g_Whh16); cudaGetSymbolAddress((void**)&Wih16, g_Wih16);
    cudaGetSymbolAddress((void**)&f116,  g_f116);  cudaGetSymbolAddress((void**)&f216,  g_f216);
    cudaGetSymbolAddress((void**)&nhh,   g_nhh);   cudaGetSymbolAddress((void**)&nhl,   g_nhl);
    cudaGetSymbolAddress((void**)&mh,    g_mh);    cudaGetSymbolAddress((void**)&ml,    g_ml);

    // prologue: fp16 conversions; bias2; h0 = 0; barrier reset; lengths dtype
    long nx4 = (long)B_ * T_ * I_ / 4;
    convh_kernel<<<(unsigned)((nx4 + 255) / 256), 256>>>(x, x16, nx4);
    convh_kernel<<<(H_ * H_ / 4 + 255) / 256, 256>>>(W_hh, Whh16, H_ * H_ / 4);
    convh_kernel<<<(H_ * I_ / 4 + 255) / 256, 256>>>(W_ih, Wih16, H_ * I_ / 4);
    convh_kernel<<<(H_ * H_ / 4 + 255) / 256, 256>>>(fc1W, f116, H_ * H_ / 4);
    convh_kernel<<<(C_ * H_ / 4 + 255) / 256, 256>>>(fc2W, f216, C_ * H_ / 4);
    init_kernel<<<(B_ * H_ + 255) / 256, 256>>>(b_ih, b_hh);
    detect_len_kernel<<<1, 1>>>((const int*)lengths);

    // whole serial chain in ONE persistent kernel
    cudaFuncSetAttribute(rnn_persistent, cudaFuncAttributeMaxDynamicSharedMemorySize, SMEM_PERS);
    rnn_persistent<<<dim3(GX, GY), NT, SMEM_PERS>>>(x16, lengths);

    // batched fc1 / fc2 over all (s, b): M = OT*B = 65536
    fc_kernel<0><<<dim3(OT_ * B_ / 64, H_ / 32), 128>>>(nhh, nhl, f116, fc1b, mh, ml, nullptr);
    fc_kernel<1><<<dim3(OT_ * B_ / 64, C_ / 32), 128>>>(mh, ml, f216, fc2b, nullptr, nullptr, out);
}